// round 1
// baseline (speedup 1.0000x reference)
#include <cuda_runtime.h>
#include <math.h>

#define NB 2
#define NT 4096
#define NC 1024
#define NH 8
#define ND 128
#define NW 512

// Scratch (allocation-free rule: __device__ globals)
__device__ float g_qkv[NB * NT * 3 * NC];   // [B*T, 3C]
__device__ float g_q[NB * NH * NT * ND];    // [B,H,T,D]
__device__ float g_k[NB * NH * NT * ND];
__device__ float g_v[NB * NH * NT * ND];
__device__ float g_att[NB * NT * NC];       // [B,T,C] (h-major inside C)

// ---------------------------------------------------------------------------
// C[M,N] = A[M,K] * B[N,K]^T   (both row-major, K%16==0, M%128==0, N%128==0)
// 128x128 block tile, BK=16, 256 threads, 8x8 per-thread (4+4 split layout)
// ---------------------------------------------------------------------------
__global__ __launch_bounds__(256, 2) void sgemm_nt(const float* __restrict__ A,
                                                   const float* __restrict__ B,
                                                   float* __restrict__ C,
                                                   int M, int N, int K)
{
    __shared__ __align__(16) float As[16][132];
    __shared__ __align__(16) float Bs[16][132];

    const int m0 = blockIdx.y * 128;
    const int n0 = blockIdx.x * 128;
    const int t  = threadIdx.x;
    const int tr = t >> 4;           // 0..15
    const int tc = t & 15;           // 0..15
    const int lrow = t >> 2;         // 0..63
    const int lc4  = (t & 3) << 2;   // 0,4,8,12

    float acc[8][8];
#pragma unroll
    for (int i = 0; i < 8; i++)
#pragma unroll
        for (int j = 0; j < 8; j++) acc[i][j] = 0.f;

    for (int k0 = 0; k0 < K; k0 += 16) {
        float4 a0 = *(const float4*)&A[(m0 + lrow) * K + k0 + lc4];
        float4 a1 = *(const float4*)&A[(m0 + lrow + 64) * K + k0 + lc4];
        float4 b0 = *(const float4*)&B[(n0 + lrow) * K + k0 + lc4];
        float4 b1 = *(const float4*)&B[(n0 + lrow + 64) * K + k0 + lc4];
#pragma unroll
        for (int e = 0; e < 4; e++) {
            As[lc4 + e][lrow]      = (&a0.x)[e];
            As[lc4 + e][lrow + 64] = (&a1.x)[e];
            Bs[lc4 + e][lrow]      = (&b0.x)[e];
            Bs[lc4 + e][lrow + 64] = (&b1.x)[e];
        }
        __syncthreads();
#pragma unroll
        for (int kk = 0; kk < 16; kk++) {
            float4 af0 = *(const float4*)&As[kk][tr * 4];
            float4 af1 = *(const float4*)&As[kk][64 + tr * 4];
            float4 bf0 = *(const float4*)&Bs[kk][tc * 4];
            float4 bf1 = *(const float4*)&Bs[kk][64 + tc * 4];
            float a[8]  = {af0.x, af0.y, af0.z, af0.w, af1.x, af1.y, af1.z, af1.w};
            float bb[8] = {bf0.x, bf0.y, bf0.z, bf0.w, bf1.x, bf1.y, bf1.z, bf1.w};
#pragma unroll
            for (int i = 0; i < 8; i++)
#pragma unroll
                for (int j = 0; j < 8; j++)
                    acc[i][j] = fmaf(a[i], bb[j], acc[i][j]);
        }
        __syncthreads();
    }

#pragma unroll
    for (int i = 0; i < 8; i++) {
        int row = m0 + ((i < 4) ? (tr * 4 + i) : (64 + tr * 4 + i - 4));
        float4 v0 = make_float4(acc[i][0], acc[i][1], acc[i][2], acc[i][3]);
        float4 v1 = make_float4(acc[i][4], acc[i][5], acc[i][6], acc[i][7]);
        *(float4*)&C[row * N + n0 + tc * 4]      = v0;
        *(float4*)&C[row * N + n0 + 64 + tc * 4] = v1;
    }
}

// ---------------------------------------------------------------------------
// RoPE + permute: g_qkv [B*T, 3C] -> g_q/g_k/g_v [B,H,T,D], rope on q,k.
// grid = B*T*H blocks, 128 threads (one per d).
// ---------------------------------------------------------------------------
__global__ void rope_split()
{
    int blk  = blockIdx.x;
    int h    = blk % NH;
    int bt   = blk / NH;          // b*NT + t
    int tpos = bt % NT;
    int b    = bt / NT;
    int d    = threadIdx.x;

    const float* base = g_qkv + (size_t)bt * (3 * NC);
    float qv = base[h * ND + d];
    float kv = base[NC + h * ND + d];
    float vv = base[2 * NC + h * ND + d];
    float qp = base[h * ND + (d ^ 64)];
    float kp = base[NC + h * ND + (d ^ 64)];

    int j = d & 63;
    double invd = pow(10000.0, -(double)j / 64.0);
    float ang = (float)tpos * (float)invd;    // fp32 product like the reference
    float cv = cosf(ang);
    float sv = sinf(ang);
    float sgn = (d < 64) ? -1.f : 1.f;

    float qo = qv * cv + sgn * qp * sv;
    float ko = kv * cv + sgn * kp * sv;

    size_t oidx = (((size_t)(b * NH + h)) * NT + tpos) * ND + d;
    g_q[oidx] = qo;
    g_k[oidx] = ko;
    g_v[oidx] = vv;
}

// ---------------------------------------------------------------------------
// Sliding-window causal flash attention, fp32.
// Block: 32 queries of one (b,h). 256 threads: thread = (qi = t/8, chunk = t%8).
// Q and O accumulators in registers (16 floats each). K/V tiles (32x128) in
// smem at pitch 132 (conflict-free float4 pattern when all lanes share kj).
// S row is reduced across the 8 lanes of a qi-group with butterfly shuffles.
// ---------------------------------------------------------------------------
__global__ __launch_bounds__(256, 2) void swa_attn()
{
    __shared__ __align__(16) float Ks[32][132];
    __shared__ __align__(16) float Vs[32][132];
    __shared__ float Ps[32][36];

    const int q0 = blockIdx.x * 32;
    const int h  = blockIdx.y;
    const int b  = blockIdx.z;
    const int t  = threadIdx.x;
    const int qi = t >> 3;
    const int ch = t & 7;
    const int ig = q0 + qi;
    const size_t headoff = ((size_t)(b * NH + h)) * NT;

    const float* Qg = g_q + (headoff + ig) * ND + ch * 16;
    float q[16], o[16];
#pragma unroll
    for (int w = 0; w < 4; w++) {
        float4 v = *(const float4*)&Qg[w * 4];
        q[w * 4 + 0] = v.x; q[w * 4 + 1] = v.y; q[w * 4 + 2] = v.z; q[w * 4 + 3] = v.w;
    }
#pragma unroll
    for (int i = 0; i < 16; i++) o[i] = 0.f;

    float m = -1e30f, l = 0.f;
    const float scale = 0.088388347648318447f;  // 1/sqrt(128)

    int kt0 = q0 - NW;
    if (kt0 < 0) kt0 = 0;

    for (int kt = kt0; kt <= q0; kt += 32) {
        __syncthreads();
        const float* Kg = g_k + (headoff + kt) * ND;
        const float* Vg = g_v + (headoff + kt) * ND;
#pragma unroll
        for (int r = 0; r < 4; r++) {
            int idx = t + 256 * r;
            int row = idx >> 5;
            int c4  = (idx & 31) << 2;
            *(float4*)&Ks[row][c4] = *(const float4*)&Kg[row * ND + c4];
            *(float4*)&Vs[row][c4] = *(const float4*)&Vg[row * ND + c4];
        }
        __syncthreads();

        // --- S = q . k, reduced across the 8 chunk-lanes of each qi-group ---
        float sv[4];
#pragma unroll
        for (int kj = 0; kj < 32; kj++) {
            const float* kr = &Ks[kj][ch * 16];
            float4 k0 = *(const float4*)&kr[0];
            float4 k1 = *(const float4*)&kr[4];
            float4 k2 = *(const float4*)&kr[8];
            float4 k3 = *(const float4*)&kr[12];
            float p;
            p = q[0] * k0.x;
            p = fmaf(q[1],  k0.y, p); p = fmaf(q[2],  k0.z, p); p = fmaf(q[3],  k0.w, p);
            p = fmaf(q[4],  k1.x, p); p = fmaf(q[5],  k1.y, p); p = fmaf(q[6],  k1.z, p);
            p = fmaf(q[7],  k1.w, p); p = fmaf(q[8],  k2.x, p); p = fmaf(q[9],  k2.y, p);
            p = fmaf(q[10], k2.z, p); p = fmaf(q[11], k2.w, p); p = fmaf(q[12], k3.x, p);
            p = fmaf(q[13], k3.y, p); p = fmaf(q[14], k3.z, p); p = fmaf(q[15], k3.w, p);
            p += __shfl_xor_sync(0xffffffffu, p, 4);
            p += __shfl_xor_sync(0xffffffffu, p, 2);
            p += __shfl_xor_sync(0xffffffffu, p, 1);
            if ((kj >> 2) == ch) sv[kj & 3] = p;   // lane ch keeps kj in [4ch, 4ch+4)
        }

        // --- mask + scale + online softmax ---
        float mt = -1e30f;
#pragma unroll
        for (int r = 0; r < 4; r++) {
            int jg = kt + ch * 4 + r;
            float s = (jg <= ig && jg >= ig - NW) ? sv[r] * scale : -1e30f;
            sv[r] = s;
            mt = fmaxf(mt, s);
        }
        mt = fmaxf(mt, __shfl_xor_sync(0xffffffffu, mt, 4));
        mt = fmaxf(mt, __shfl_xor_sync(0xffffffffu, mt, 2));
        mt = fmaxf(mt, __shfl_xor_sync(0xffffffffu, mt, 1));

        float mnew  = fmaxf(m, mt);
        float alpha = __expf(m - mnew);
        float rl = 0.f;
#pragma unroll
        for (int r = 0; r < 4; r++) {
            float p = __expf(sv[r] - mnew);
            Ps[qi][ch * 4 + r] = p;
            rl += p;
        }
        rl += __shfl_xor_sync(0xffffffffu, rl, 4);
        rl += __shfl_xor_sync(0xffffffffu, rl, 2);
        rl += __shfl_xor_sync(0xffffffffu, rl, 1);
        l = l * alpha + rl;
        m = mnew;
#pragma unroll
        for (int i = 0; i < 16; i++) o[i] *= alpha;
        __syncwarp();

        // --- O += P @ V ---
#pragma unroll
        for (int kj = 0; kj < 32; kj++) {
            float p = Ps[qi][kj];
            const float* vr = &Vs[kj][ch * 16];
            float4 v0 = *(const float4*)&vr[0];
            float4 v1 = *(const float4*)&vr[4];
            float4 v2 = *(const float4*)&vr[8];
            float4 v3 = *(const float4*)&vr[12];
            o[0]  = fmaf(p, v0.x, o[0]);  o[1]  = fmaf(p, v0.y, o[1]);
            o[2]  = fmaf(p, v0.z, o[2]);  o[3]  = fmaf(p, v0.w, o[3]);
            o[4]  = fmaf(p, v1.x, o[4]);  o[5]  = fmaf(p, v1.y, o[5]);
            o[6]  = fmaf(p, v1.z, o[6]);  o[7]  = fmaf(p, v1.w, o[7]);
            o[8]  = fmaf(p, v2.x, o[8]);  o[9]  = fmaf(p, v2.y, o[9]);
            o[10] = fmaf(p, v2.z, o[10]); o[11] = fmaf(p, v2.w, o[11]);
            o[12] = fmaf(p, v3.x, o[12]); o[13] = fmaf(p, v3.y, o[13]);
            o[14] = fmaf(p, v3.z, o[14]); o[15] = fmaf(p, v3.w, o[15]);
        }
    }

    float invl = 1.f / l;
    float* Og = g_att + ((size_t)(b * NT + ig)) * NC + h * ND + ch * 16;
#pragma unroll
    for (int w = 0; w < 4; w++) {
        float4 v = make_float4(o[w * 4] * invl, o[w * 4 + 1] * invl,
                               o[w * 4 + 2] * invl, o[w * 4 + 3] * invl);
        *(float4*)&Og[w * 4] = v;
    }
}

// ---------------------------------------------------------------------------
extern "C" void kernel_launch(void* const* d_in, const int* in_sizes, int n_in,
                              void* d_out, int out_size)
{
    const float* x     = (const float*)d_in[0];
    const float* w_qkv = (const float*)d_in[1];
    const float* w_o   = (const float*)d_in[2];
    float* out = (float*)d_out;

    float *qkv_ptr, *att_ptr;
    cudaGetSymbolAddress((void**)&qkv_ptr, g_qkv);
    cudaGetSymbolAddress((void**)&att_ptr, g_att);

    // 1) QKV projection: [8192,1024] x [3072,1024]^T
    sgemm_nt<<<dim3(3 * NC / 128, NB * NT / 128), 256>>>(x, w_qkv, qkv_ptr,
                                                         NB * NT, 3 * NC, NC);
    // 2) RoPE + head permute
    rope_split<<<NB * NT * NH, ND>>>();
    // 3) Sliding-window attention
    swa_attn<<<dim3(NT / 32, NH, NB), 256>>>();
    // 4) Output projection: [8192,1024] x [1024,1024]^T
    sgemm_nt<<<dim3(NC / 128, NB * NT / 128), 256>>>(att_ptr, w_o, out,
                                                     NB * NT, NC, NC);
}

// round 2
// speedup vs baseline: 1.9143x; 1.9143x over previous
#include <cuda_runtime.h>
#include <math.h>

#define NB 2
#define NT 4096
#define NC 1024
#define NH 8
#define ND 128
#define NW 512

#define BQ 64
#define BK 64

// Scratch (allocation-free rule: __device__ globals)
__device__ float g_qkv[NB * NT * 3 * NC];   // [B*T, 3C]
__device__ float g_q[NB * NH * NT * ND];    // [B,H,T,D]
__device__ float g_k[NB * NH * NT * ND];
__device__ float g_v[NB * NH * NT * ND];
__device__ float g_att[NB * NT * NC];       // [B,T,C] (h-major inside C)

// ---------------------------------------------------------------------------
// C[M,N] = A[M,K] * B[N,K]^T   (both row-major, K%16==0, M%128==0, N%128==0)
// ---------------------------------------------------------------------------
__global__ __launch_bounds__(256, 2) void sgemm_nt(const float* __restrict__ A,
                                                   const float* __restrict__ B,
                                                   float* __restrict__ C,
                                                   int M, int N, int K)
{
    __shared__ __align__(16) float As[16][132];
    __shared__ __align__(16) float Bs[16][132];

    const int m0 = blockIdx.y * 128;
    const int n0 = blockIdx.x * 128;
    const int t  = threadIdx.x;
    const int tr = t >> 4;
    const int tc = t & 15;
    const int lrow = t >> 2;
    const int lc4  = (t & 3) << 2;

    float acc[8][8];
#pragma unroll
    for (int i = 0; i < 8; i++)
#pragma unroll
        for (int j = 0; j < 8; j++) acc[i][j] = 0.f;

    for (int k0 = 0; k0 < K; k0 += 16) {
        float4 a0 = *(const float4*)&A[(m0 + lrow) * K + k0 + lc4];
        float4 a1 = *(const float4*)&A[(m0 + lrow + 64) * K + k0 + lc4];
        float4 b0 = *(const float4*)&B[(n0 + lrow) * K + k0 + lc4];
        float4 b1 = *(const float4*)&B[(n0 + lrow + 64) * K + k0 + lc4];
#pragma unroll
        for (int e = 0; e < 4; e++) {
            As[lc4 + e][lrow]      = (&a0.x)[e];
            As[lc4 + e][lrow + 64] = (&a1.x)[e];
            Bs[lc4 + e][lrow]      = (&b0.x)[e];
            Bs[lc4 + e][lrow + 64] = (&b1.x)[e];
        }
        __syncthreads();
#pragma unroll
        for (int kk = 0; kk < 16; kk++) {
            float4 af0 = *(const float4*)&As[kk][tr * 4];
            float4 af1 = *(const float4*)&As[kk][64 + tr * 4];
            float4 bf0 = *(const float4*)&Bs[kk][tc * 4];
            float4 bf1 = *(const float4*)&Bs[kk][64 + tc * 4];
            float a[8]  = {af0.x, af0.y, af0.z, af0.w, af1.x, af1.y, af1.z, af1.w};
            float bb[8] = {bf0.x, bf0.y, bf0.z, bf0.w, bf1.x, bf1.y, bf1.z, bf1.w};
#pragma unroll
            for (int i = 0; i < 8; i++)
#pragma unroll
                for (int j = 0; j < 8; j++)
                    acc[i][j] = fmaf(a[i], bb[j], acc[i][j]);
        }
        __syncthreads();
    }

#pragma unroll
    for (int i = 0; i < 8; i++) {
        int row = m0 + ((i < 4) ? (tr * 4 + i) : (64 + tr * 4 + i - 4));
        float4 v0 = make_float4(acc[i][0], acc[i][1], acc[i][2], acc[i][3]);
        float4 v1 = make_float4(acc[i][4], acc[i][5], acc[i][6], acc[i][7]);
        *(float4*)&C[row * N + n0 + tc * 4]      = v0;
        *(float4*)&C[row * N + n0 + 64 + tc * 4] = v1;
    }
}

// ---------------------------------------------------------------------------
// RoPE + permute
// ---------------------------------------------------------------------------
__global__ void rope_split()
{
    int blk  = blockIdx.x;
    int h    = blk % NH;
    int bt   = blk / NH;
    int tpos = bt % NT;
    int b    = bt / NT;
    int d    = threadIdx.x;

    const float* base = g_qkv + (size_t)bt * (3 * NC);
    float qv = base[h * ND + d];
    float kv = base[NC + h * ND + d];
    float vv = base[2 * NC + h * ND + d];
    float qp = base[h * ND + (d ^ 64)];
    float kp = base[NC + h * ND + (d ^ 64)];

    int j = d & 63;
    double invd = pow(10000.0, -(double)j / 64.0);
    float ang = (float)tpos * (float)invd;
    float cv = cosf(ang);
    float sv = sinf(ang);
    float sgn = (d < 64) ? -1.f : 1.f;

    float qo = qv * cv + sgn * qp * sv;
    float ko = kv * cv + sgn * kp * sv;

    size_t oidx = (((size_t)(b * NH + h)) * NT + tpos) * ND + d;
    g_q[oidx] = qo;
    g_k[oidx] = ko;
    g_v[oidx] = vv;
}

// ---------------------------------------------------------------------------
// Sliding-window flash attention, GEMM-structured.
// Block: BQ=64 queries of one (b,h), 256 threads.
// thread = (ty = t/16 in 0..15, tx = t%16). S fragment 4x4 (rows ty*4+i,
// cols tx*4+j), O fragment 4x8 (rows ty*4+i, dcols tx*8+j).
// Smem (dynamic): Qs[128][68] d-major, Ks[128][68] d-major, Vs[64][132],
// Ps[64][68]. Row stats via xor-shuffles over the 16 lanes sharing a row.
// ---------------------------------------------------------------------------
#define QP 68
#define VP 132
#define SM_Q   0
#define SM_K   (128 * QP)
#define SM_V   (2 * 128 * QP)
#define SM_P   (2 * 128 * QP + BK * VP)
#define SM_FLOATS (SM_P + BQ * QP)

__global__ __launch_bounds__(256, 1) void swa_attn()
{
    extern __shared__ __align__(16) float sm[];
    float* Qs = sm + SM_Q;
    float* Ks = sm + SM_K;
    float* Vs = sm + SM_V;
    float* Ps = sm + SM_P;

    const int q0 = blockIdx.x * BQ;
    const int h  = blockIdx.y;
    const int b  = blockIdx.z;
    const int t  = threadIdx.x;
    const int ty = t >> 4;          // 0..15
    const int tx = t & 15;          // 0..15
    const int ty4 = ty * 4;
    const size_t headoff = ((size_t)(b * NH + h)) * NT;

    // transpose-loader mapping: 4 consecutive lanes share a row, read 64B chunks
    const int lrow = t >> 2;        // 0..63
    const int lsub = t & 3;         // 0..3

    // ---- load Q tile, d-major (persists across key tiles) ----
    {
        const float* Qg = g_q + (headoff + q0) * ND;
#pragma unroll
        for (int w = 0; w < 8; w++) {
            int d4 = (lsub + 4 * w) * 4;     // 0,16,..,124 offset by lsub*4
            float4 v = *(const float4*)&Qg[lrow * ND + d4];
            Qs[(d4 + 0) * QP + lrow] = v.x;
            Qs[(d4 + 1) * QP + lrow] = v.y;
            Qs[(d4 + 2) * QP + lrow] = v.z;
            Qs[(d4 + 3) * QP + lrow] = v.w;
        }
    }

    float o[4][8];
    float m[4], l[4];
#pragma unroll
    for (int i = 0; i < 4; i++) {
        m[i] = -1e30f; l[i] = 0.f;
#pragma unroll
        for (int j = 0; j < 8; j++) o[i][j] = 0.f;
    }

    const float scale = 0.088388347648318447f;  // 1/sqrt(128)
    int kt0 = q0 - NW;
    if (kt0 < 0) kt0 = 0;

    for (int kt = kt0; kt <= q0; kt += BK) {
        __syncthreads();   // protect prev tile's Vs/Ps (and Ks) from overwrite

        // ---- load K tile (d-major) and V tile (natural) ----
        {
            const float* Kg = g_k + (headoff + kt) * ND;
            const float* Vg = g_v + (headoff + kt) * ND;
#pragma unroll
            for (int w = 0; w < 8; w++) {
                int d4 = (lsub + 4 * w) * 4;
                float4 v = *(const float4*)&Kg[lrow * ND + d4];
                Ks[(d4 + 0) * QP + lrow] = v.x;
                Ks[(d4 + 1) * QP + lrow] = v.y;
                Ks[(d4 + 2) * QP + lrow] = v.z;
                Ks[(d4 + 3) * QP + lrow] = v.w;
            }
#pragma unroll
            for (int w = 0; w < 8; w++) {
                int lin = t + 256 * w;
                int vr  = lin >> 5;
                int c4  = (lin & 31) << 2;
                *(float4*)&Vs[vr * VP + c4] = *(const float4*)&Vg[vr * ND + c4];
            }
        }
        __syncthreads();

        // ---- S = Q . K^T  (64x64x128 register GEMM) ----
        float s[4][4];
#pragma unroll
        for (int i = 0; i < 4; i++)
#pragma unroll
            for (int j = 0; j < 4; j++) s[i][j] = 0.f;

#pragma unroll 4
        for (int kk = 0; kk < ND; kk++) {
            float4 qf = *(const float4*)&Qs[kk * QP + ty4];
            float4 kf = *(const float4*)&Ks[kk * QP + tx * 4];
            float qa[4] = {qf.x, qf.y, qf.z, qf.w};
            float ka[4] = {kf.x, kf.y, kf.z, kf.w};
#pragma unroll
            for (int i = 0; i < 4; i++)
#pragma unroll
                for (int j = 0; j < 4; j++)
                    s[i][j] = fmaf(qa[i], ka[j], s[i][j]);
        }

        // ---- mask + scale + online softmax on fragments ----
#pragma unroll
        for (int i = 0; i < 4; i++) {
            int ig = q0 + ty4 + i;
            float rm = -1e30f;
#pragma unroll
            for (int j = 0; j < 4; j++) {
                int jg = kt + tx * 4 + j;
                float v = (jg <= ig && jg >= ig - NW) ? s[i][j] * scale : -1e30f;
                s[i][j] = v;
                rm = fmaxf(rm, v);
            }
            rm = fmaxf(rm, __shfl_xor_sync(0xffffffffu, rm, 1));
            rm = fmaxf(rm, __shfl_xor_sync(0xffffffffu, rm, 2));
            rm = fmaxf(rm, __shfl_xor_sync(0xffffffffu, rm, 4));
            rm = fmaxf(rm, __shfl_xor_sync(0xffffffffu, rm, 8));

            float mnew  = fmaxf(m[i], rm);
            float alpha = __expf(m[i] - mnew);
            m[i] = mnew;

            float rs = 0.f;
            float4 pv;
#pragma unroll
            for (int j = 0; j < 4; j++) {
                float p = __expf(s[i][j] - mnew);
                (&pv.x)[j] = p;
                rs += p;
            }
            rs += __shfl_xor_sync(0xffffffffu, rs, 1);
            rs += __shfl_xor_sync(0xffffffffu, rs, 2);
            rs += __shfl_xor_sync(0xffffffffu, rs, 4);
            rs += __shfl_xor_sync(0xffffffffu, rs, 8);
            l[i] = l[i] * alpha + rs;

#pragma unroll
            for (int j = 0; j < 8; j++) o[i][j] *= alpha;

            *(float4*)&Ps[(ty4 + i) * QP + tx * 4] = pv;
        }
        __syncthreads();

        // ---- O += P @ V  (64x128x64 register GEMM, kk unrolled by 4) ----
        for (int kk = 0; kk < BK; kk += 4) {
            float4 p0 = *(const float4*)&Ps[(ty4 + 0) * QP + kk];
            float4 p1 = *(const float4*)&Ps[(ty4 + 1) * QP + kk];
            float4 p2 = *(const float4*)&Ps[(ty4 + 2) * QP + kk];
            float4 p3 = *(const float4*)&Ps[(ty4 + 3) * QP + kk];
            float pr[4][4] = {{p0.x, p0.y, p0.z, p0.w},
                              {p1.x, p1.y, p1.z, p1.w},
                              {p2.x, p2.y, p2.z, p2.w},
                              {p3.x, p3.y, p3.z, p3.w}};
#pragma unroll
            for (int u = 0; u < 4; u++) {
                float4 v0 = *(const float4*)&Vs[(kk + u) * VP + tx * 8];
                float4 v1 = *(const float4*)&Vs[(kk + u) * VP + tx * 8 + 4];
                float va[8] = {v0.x, v0.y, v0.z, v0.w, v1.x, v1.y, v1.z, v1.w};
#pragma unroll
                for (int i = 0; i < 4; i++)
#pragma unroll
                    for (int j = 0; j < 8; j++)
                        o[i][j] = fmaf(pr[i][u], va[j], o[i][j]);
            }
        }
    }

    // ---- finalize + store ----
#pragma unroll
    for (int i = 0; i < 4; i++) {
        float inv = 1.f / l[i];
        int ig = q0 + ty4 + i;
        float* Og = g_att + ((size_t)(b * NT + ig)) * NC + h * ND + tx * 8;
        float4 v0 = make_float4(o[i][0] * inv, o[i][1] * inv, o[i][2] * inv, o[i][3] * inv);
        float4 v1 = make_float4(o[i][4] * inv, o[i][5] * inv, o[i][6] * inv, o[i][7] * inv);
        *(float4*)&Og[0] = v0;
        *(float4*)&Og[4] = v1;
    }
}

// ---------------------------------------------------------------------------
extern "C" void kernel_launch(void* const* d_in, const int* in_sizes, int n_in,
                              void* d_out, int out_size)
{
    const float* x     = (const float*)d_in[0];
    const float* w_qkv = (const float*)d_in[1];
    const float* w_o   = (const float*)d_in[2];
    float* out = (float*)d_out;

    float *qkv_ptr, *att_ptr;
    cudaGetSymbolAddress((void**)&qkv_ptr, g_qkv);
    cudaGetSymbolAddress((void**)&att_ptr, g_att);

    static int smem_set = 0;
    if (!smem_set) {
        cudaFuncSetAttribute(swa_attn, cudaFuncAttributeMaxDynamicSharedMemorySize,
                             SM_FLOATS * (int)sizeof(float));
        smem_set = 1;
    }

    // 1) QKV projection
    sgemm_nt<<<dim3(3 * NC / 128, NB * NT / 128), 256>>>(x, w_qkv, qkv_ptr,
                                                         NB * NT, 3 * NC, NC);
    // 2) RoPE + head permute
    rope_split<<<NB * NT * NH, ND>>>();
    // 3) Sliding-window attention
    swa_attn<<<dim3(NT / BQ, NH, NB), 256, SM_FLOATS * sizeof(float)>>>();
    // 4) Output projection
    sgemm_nt<<<dim3(NC / 128, NB * NT / 128), 256>>>(att_ptr, w_o, out,
                                                     NB * NT, NC, NC);
}

// round 4
// speedup vs baseline: 2.5355x; 1.3245x over previous
#include <cuda_runtime.h>
#include <cuda_bf16.h>
#include <math.h>
#include <cstdint>

#define NB 2
#define NT 4096
#define NC 1024
#define NH 8
#define ND 128
#define NW 512

#define BQ 64
#define BK 64

// ---------------- scratch (__device__ globals; no allocs allowed) ----------
__device__ float g_qkv[NB * NT * 3 * NC];   // [B*T, 3C]
__device__ float g_q[NB * NH * NT * ND];    // [B,H,T,D]
__device__ float g_k[NB * NH * NT * ND];
__device__ float g_v[NB * NH * NT * ND];
__device__ float g_att[NB * NT * NC];       // [B,T,C]

__device__ __nv_bfloat16 g_xh[NB * NT * NC], g_xl[NB * NT * NC];
__device__ __nv_bfloat16 g_wqh[3 * NC * NC], g_wql[3 * NC * NC];
__device__ __nv_bfloat16 g_woh[NC * NC],     g_wol[NC * NC];
__device__ __nv_bfloat16 g_ah[NB * NT * NC], g_al[NB * NT * NC];

// ---------------- helpers ---------------------------------------------------
__device__ __forceinline__ uint32_t smem_u32(const void* p) {
    uint32_t a;
    asm("{ .reg .u64 t; cvta.to.shared.u64 t, %1; cvt.u32.u64 %0, t; }" : "=r"(a) : "l"(p));
    return a;
}

// tile layout: gmem row r (64B of bf16 data) -> smem offset
// (r/2)*128 + (r%2)*64 + cu*16, then SW128 xor swizzle. 64 smem rows x 128B.
__device__ __forceinline__ uint32_t toff(int r, int cu) {
    uint32_t o = ((uint32_t)(r >> 1) << 7) + ((uint32_t)(r & 1) << 6) + ((uint32_t)cu << 4);
    return o ^ ((o >> 3) & 0x70);
}

#define LDSM4(r0, r1, r2, r3, ad) \
    asm volatile("ldmatrix.sync.aligned.m8n8.x4.shared.b16 {%0,%1,%2,%3}, [%4];" \
                 : "=r"(r0), "=r"(r1), "=r"(r2), "=r"(r3) : "r"(ad))

#define MMA16816(d, a0, a1, a2, a3, b0, b1) \
    asm volatile("mma.sync.aligned.m16n8k16.row.col.f32.bf16.bf16.f32 " \
                 "{%0,%1,%2,%3},{%4,%5,%6,%7},{%8,%9},{%0,%1,%2,%3};" \
                 : "+f"((d)[0]), "+f"((d)[1]), "+f"((d)[2]), "+f"((d)[3]) \
                 : "r"(a0), "r"(a1), "r"(a2), "r"(a3), "r"(b0), "r"(b1))

#define CP_ASYNC16(sa, ga) \
    asm volatile("cp.async.cg.shared.global [%0], [%1], 16;" :: "r"(sa), "l"(ga))
#define CP_COMMIT() asm volatile("cp.async.commit_group;" ::: "memory")
#define CP_WAIT1()  asm volatile("cp.async.wait_group 1;" ::: "memory")
#define CP_WAIT0()  asm volatile("cp.async.wait_group 0;" ::: "memory")

// ---------------------------------------------------------------------------
// fp32 -> (hi, lo) bf16 split
// ---------------------------------------------------------------------------
__global__ void conv_split(const float* __restrict__ s, __nv_bfloat16* __restrict__ h,
                           __nv_bfloat16* __restrict__ l, int n)
{
    int i = (blockIdx.x * 256 + threadIdx.x) * 4;
    if (i >= n) return;
    float4 v = *(const float4*)&s[i];
    float vv[4] = {v.x, v.y, v.z, v.w};
    __nv_bfloat16 hb[4], lb[4];
#pragma unroll
    for (int e = 0; e < 4; e++) {
        hb[e] = __float2bfloat16(vv[e]);
        lb[e] = __float2bfloat16(vv[e] - __bfloat162float(hb[e]));
    }
    *(uint2*)&h[i] = *(uint2*)hb;
    *(uint2*)&l[i] = *(uint2*)lb;
}

// ---------------------------------------------------------------------------
// C[M,N] = A[M,K] . B[N,K]^T via mma.sync bf16 with hi/lo compensation.
// CTA 128x128, K-tile 32, 256 threads (8 warps = 4m x 2n), double-buffered
// cp.async. smem/stage: Ah | Al | Bh | Bl tiles, 8KB each (64 rows x 128B,
// SW128 swizzled); 2 stages = 64KB dynamic.
// ---------------------------------------------------------------------------
#define GSTAGE 32768
#define GSMEM  (2 * GSTAGE)

__global__ __launch_bounds__(256) void gemm_mma(
    const __nv_bfloat16* __restrict__ Ah, const __nv_bfloat16* __restrict__ Al,
    const __nv_bfloat16* __restrict__ Bh, const __nv_bfloat16* __restrict__ Bl,
    float* __restrict__ C, int M, int N, int K)
{
    extern __shared__ __align__(1024) char smem[];
    const uint32_t sb = smem_u32(smem);
    const int t = threadIdx.x;
    const int wid = t >> 5, lane = t & 31;
    const int m0 = blockIdx.y * 128, n0 = blockIdx.x * 128;
    const int wm = (wid & 3) * 32;       // warp m offset (within 128)
    const int wn = (wid >> 2) * 64;      // warp n offset

    const size_t kb = (size_t)K * 2;     // gmem row stride bytes
    const char* gA[4] = {
        (const char*)(Ah + (size_t)m0 * K), (const char*)(Al + (size_t)m0 * K),
        (const char*)(Bh + (size_t)n0 * K), (const char*)(Bl + (size_t)n0 * K)};

    const int r_ld = t >> 2, cu_ld = t & 3;            // this thread's 2 units
    const uint32_t so0 = toff(r_ld, cu_ld);            // unit t
    const int r_ld2 = (t + 256) >> 2;                  // unit t+256 (rows 64..127? no)
    // 512 units/tile: unit = t and t+256 -> r = unit>>2 in [0,128)
    const int cu_ld2 = (t + 256) & 3;
    const uint32_t so1 = toff(r_ld2 & 127, cu_ld2);    // r in [64,128) maps same tile? r<128
    // NOTE: tile has 128 gmem rows (r 0..127), 4 units each = 512 units. ok.

    const int nt = K / 32;

    // ---- stage issue ----
    auto issue = [&](int buf, int k0) {
        uint32_t stage = sb + buf * GSTAGE;
#pragma unroll
        for (int tile = 0; tile < 4; tile++) {
            const char* g = gA[tile] + (size_t)k0 * 2;
            uint32_t stb = stage + tile * 8192;
            CP_ASYNC16(stb + so0, g + (size_t)r_ld * kb + cu_ld * 16);
            CP_ASYNC16(stb + so1, g + (size_t)r_ld2 * kb + cu_ld2 * 16);
        }
        CP_COMMIT();
    };

    float acc[2][8][4];
#pragma unroll
    for (int i = 0; i < 2; i++)
#pragma unroll
        for (int j = 0; j < 8; j++)
#pragma unroll
            for (int e = 0; e < 4; e++) acc[i][j][e] = 0.f;

    issue(0, 0);

    // precomputed ldmatrix lane-address components
    const int a_row = (lane & 7) + ((lane >> 3) & 1) * 8;   // + m frag base
    const int a_ku  = lane >> 4;                            // + kstep*2
    const int b_row = (lane & 7) + ((lane >> 4) & 1) * 8;   // + n group base
    const int b_ku  = (lane >> 3) & 1;

    for (int tt = 0; tt < nt; tt++) {
        if (tt + 1 < nt) { issue((tt + 1) & 1, (tt + 1) * 32); CP_WAIT1(); }
        else             { CP_WAIT0(); }
        __syncthreads();

        const uint32_t stg = sb + (tt & 1) * GSTAGE;
#pragma unroll
        for (int ks = 0; ks < 2; ks++) {
            const int ku = ks * 2;
            uint32_t ah[2][4], al[2][4];
#pragma unroll
            for (int i = 0; i < 2; i++) {
                uint32_t ad = stg + toff(wm + i * 16 + a_row, ku + a_ku);
                LDSM4(ah[i][0], ah[i][1], ah[i][2], ah[i][3], ad);
                uint32_t ad2 = ad + 8192;
                LDSM4(al[i][0], al[i][1], al[i][2], al[i][3], ad2);
            }
#pragma unroll
            for (int jj = 0; jj < 4; jj++) {
                uint32_t bd = stg + 16384 + toff(wn + jj * 16 + b_row, ku + b_ku);
                uint32_t bh0, bh1, bh2, bh3, bl0, bl1, bl2, bl3;
                LDSM4(bh0, bh1, bh2, bh3, bd);
                LDSM4(bl0, bl1, bl2, bl3, bd + 8192);
#pragma unroll
                for (int i = 0; i < 2; i++) {
                    MMA16816(acc[i][jj * 2],     ah[i][0], ah[i][1], ah[i][2], ah[i][3], bh0, bh1);
                    MMA16816(acc[i][jj * 2],     ah[i][0], ah[i][1], ah[i][2], ah[i][3], bl0, bl1);
                    MMA16816(acc[i][jj * 2],     al[i][0], al[i][1], al[i][2], al[i][3], bh0, bh1);
                    MMA16816(acc[i][jj * 2 + 1], ah[i][0], ah[i][1], ah[i][2], ah[i][3], bh2, bh3);
                    MMA16816(acc[i][jj * 2 + 1], ah[i][0], ah[i][1], ah[i][2], ah[i][3], bl2, bl3);
                    MMA16816(acc[i][jj * 2 + 1], al[i][0], al[i][1], al[i][2], al[i][3], bh2, bh3);
                }
            }
        }
        __syncthreads();
    }

    // ---- epilogue: direct fp32 stores ----
#pragma unroll
    for (int i = 0; i < 2; i++) {
#pragma unroll
        for (int j = 0; j < 8; j++) {
            int row = m0 + wm + i * 16 + (lane >> 2);
            int col = n0 + wn + j * 8 + (lane & 3) * 2;
            *(float2*)&C[(size_t)row * N + col] = make_float2(acc[i][j][0], acc[i][j][1]);
            *(float2*)&C[(size_t)(row + 8) * N + col] = make_float2(acc[i][j][2], acc[i][j][3]);
        }
    }
}

// ---------------------------------------------------------------------------
// RoPE + permute
// ---------------------------------------------------------------------------
__global__ void rope_split()
{
    int blk  = blockIdx.x;
    int h    = blk % NH;
    int bt   = blk / NH;
    int tpos = bt % NT;
    int b    = bt / NT;
    int d    = threadIdx.x;

    const float* base = g_qkv + (size_t)bt * (3 * NC);
    float qv = base[h * ND + d];
    float kv = base[NC + h * ND + d];
    float vv = base[2 * NC + h * ND + d];
    float qp = base[h * ND + (d ^ 64)];
    float kp = base[NC + h * ND + (d ^ 64)];

    int j = d & 63;
    double invd = pow(10000.0, -(double)j / 64.0);
    float ang = (float)tpos * (float)invd;
    float cv = cosf(ang);
    float sv = sinf(ang);
    float sgn = (d < 64) ? -1.f : 1.f;

    float qo = qv * cv + sgn * qp * sv;
    float ko = kv * cv + sgn * kp * sv;

    size_t oidx = (((size_t)(b * NH + h)) * NT + tpos) * ND + d;
    g_q[oidx] = qo;
    g_k[oidx] = ko;
    g_v[oidx] = vv;
}

// ---------------------------------------------------------------------------
// Sliding-window flash attention (fp32 register GEMM version, unchanged)
// ---------------------------------------------------------------------------
#define QP 68
#define VP 132
#define SM_Q   0
#define SM_K   (128 * QP)
#define SM_V   (2 * 128 * QP)
#define SM_P   (2 * 128 * QP + BK * VP)
#define SM_FLOATS (SM_P + BQ * QP)

__global__ __launch_bounds__(256, 1) void swa_attn()
{
    extern __shared__ __align__(16) float sm[];
    float* Qs = sm + SM_Q;
    float* Ks = sm + SM_K;
    float* Vs = sm + SM_V;
    float* Ps = sm + SM_P;

    const int q0 = blockIdx.x * BQ;
    const int h  = blockIdx.y;
    const int b  = blockIdx.z;
    const int t  = threadIdx.x;
    const int ty = t >> 4;
    const int tx = t & 15;
    const int ty4 = ty * 4;
    const size_t headoff = ((size_t)(b * NH + h)) * NT;

    const int lrow = t >> 2;
    const int lsub = t & 3;

    {
        const float* Qg = g_q + (headoff + q0) * ND;
#pragma unroll
        for (int w = 0; w < 8; w++) {
            int d4 = (lsub + 4 * w) * 4;
            float4 v = *(const float4*)&Qg[lrow * ND + d4];
            Qs[(d4 + 0) * QP + lrow] = v.x;
            Qs[(d4 + 1) * QP + lrow] = v.y;
            Qs[(d4 + 2) * QP + lrow] = v.z;
            Qs[(d4 + 3) * QP + lrow] = v.w;
        }
    }

    float o[4][8];
    float m[4], l[4];
#pragma unroll
    for (int i = 0; i < 4; i++) {
        m[i] = -1e30f; l[i] = 0.f;
#pragma unroll
        for (int j = 0; j < 8; j++) o[i][j] = 0.f;
    }

    const float scale = 0.088388347648318447f;
    int kt0 = q0 - NW;
    if (kt0 < 0) kt0 = 0;

    for (int kt = kt0; kt <= q0; kt += BK) {
        __syncthreads();
        {
            const float* Kg = g_k + (headoff + kt) * ND;
            const float* Vg = g_v + (headoff + kt) * ND;
#pragma unroll
            for (int w = 0; w < 8; w++) {
                int d4 = (lsub + 4 * w) * 4;
                float4 v = *(const float4*)&Kg[lrow * ND + d4];
                Ks[(d4 + 0) * QP + lrow] = v.x;
                Ks[(d4 + 1) * QP + lrow] = v.y;
                Ks[(d4 + 2) * QP + lrow] = v.z;
                Ks[(d4 + 3) * QP + lrow] = v.w;
            }
#pragma unroll
            for (int w = 0; w < 8; w++) {
                int lin = t + 256 * w;
                int vr  = lin >> 5;
                int c4  = (lin & 31) << 2;
                *(float4*)&Vs[vr * VP + c4] = *(const float4*)&Vg[vr * ND + c4];
            }
        }
        __syncthreads();

        float s[4][4];
#pragma unroll
        for (int i = 0; i < 4; i++)
#pragma unroll
            for (int j = 0; j < 4; j++) s[i][j] = 0.f;

#pragma unroll 4
        for (int kk = 0; kk < ND; kk++) {
            float4 qf = *(const float4*)&Qs[kk * QP + ty4];
            float4 kf = *(const float4*)&Ks[kk * QP + tx * 4];
            float qa[4] = {qf.x, qf.y, qf.z, qf.w};
            float ka[4] = {kf.x, kf.y, kf.z, kf.w};
#pragma unroll
            for (int i = 0; i < 4; i++)
#pragma unroll
                for (int j = 0; j < 4; j++)
                    s[i][j] = fmaf(qa[i], ka[j], s[i][j]);
        }

#pragma unroll
        for (int i = 0; i < 4; i++) {
            int ig = q0 + ty4 + i;
            float rm = -1e30f;
#pragma unroll
            for (int j = 0; j < 4; j++) {
                int jg = kt + tx * 4 + j;
                float v = (jg <= ig && jg >= ig - NW) ? s[i][j] * scale : -1e30f;
                s[i][j] = v;
                rm = fmaxf(rm, v);
            }
            rm = fmaxf(rm, __shfl_xor_sync(0xffffffffu, rm, 1));
            rm = fmaxf(rm, __shfl_xor_sync(0xffffffffu, rm, 2));
            rm = fmaxf(rm, __shfl_xor_sync(0xffffffffu, rm, 4));
            rm = fmaxf(rm, __shfl_xor_sync(0xffffffffu, rm, 8));

            float mnew  = fmaxf(m[i], rm);
            float alpha = __expf(m[i] - mnew);
            m[i] = mnew;

            float rs = 0.f;
            float4 pv;
#pragma unroll
            for (int j = 0; j < 4; j++) {
                float p = __expf(s[i][j] - mnew);
                (&pv.x)[j] = p;
                rs += p;
            }
            rs += __shfl_xor_sync(0xffffffffu, rs, 1);
            rs += __shfl_xor_sync(0xffffffffu, rs, 2);
            rs += __shfl_xor_sync(0xffffffffu, rs, 4);
            rs += __shfl_xor_sync(0xffffffffu, rs, 8);
            l[i] = l[i] * alpha + rs;

#pragma unroll
            for (int j = 0; j < 8; j++) o[i][j] *= alpha;

            *(float4*)&Ps[(ty4 + i) * QP + tx * 4] = pv;
        }
        __syncthreads();

        for (int kk = 0; kk < BK; kk += 4) {
            float4 p0 = *(const float4*)&Ps[(ty4 + 0) * QP + kk];
            float4 p1 = *(const float4*)&Ps[(ty4 + 1) * QP + kk];
            float4 p2 = *(const float4*)&Ps[(ty4 + 2) * QP + kk];
            float4 p3 = *(const float4*)&Ps[(ty4 + 3) * QP + kk];
            float pr[4][4] = {{p0.x, p0.y, p0.z, p0.w},
                              {p1.x, p1.y, p1.z, p1.w},
                              {p2.x, p2.y, p2.z, p2.w},
                              {p3.x, p3.y, p3.z, p3.w}};
#pragma unroll
            for (int u = 0; u < 4; u++) {
                float4 v0 = *(const float4*)&Vs[(kk + u) * VP + tx * 8];
                float4 v1 = *(const float4*)&Vs[(kk + u) * VP + tx * 8 + 4];
                float va[8] = {v0.x, v0.y, v0.z, v0.w, v1.x, v1.y, v1.z, v1.w};
#pragma unroll
                for (int i = 0; i < 4; i++)
#pragma unroll
                    for (int j = 0; j < 8; j++)
                        o[i][j] = fmaf(pr[i][u], va[j], o[i][j]);
            }
        }
    }

#pragma unroll
    for (int i = 0; i < 4; i++) {
        float inv = 1.f / l[i];
        int ig = q0 + ty4 + i;
        float* Og = g_att + ((size_t)(b * NT + ig)) * NC + h * ND + tx * 8;
        float4 v0 = make_float4(o[i][0] * inv, o[i][1] * inv, o[i][2] * inv, o[i][3] * inv);
        float4 v1 = make_float4(o[i][4] * inv, o[i][5] * inv, o[i][6] * inv, o[i][7] * inv);
        *(float4*)&Og[0] = v0;
        *(float4*)&Og[4] = v1;
    }
}

// ---------------------------------------------------------------------------
extern "C" void kernel_launch(void* const* d_in, const int* in_sizes, int n_in,
                              void* d_out, int out_size)
{
    const float* x     = (const float*)d_in[0];
    const float* w_qkv = (const float*)d_in[1];
    const float* w_o   = (const float*)d_in[2];
    float* out = (float*)d_out;

    float *qkv_ptr, *att_ptr;
    cudaGetSymbolAddress((void**)&qkv_ptr, g_qkv);
    cudaGetSymbolAddress((void**)&att_ptr, g_att);
    __nv_bfloat16 *xh, *xl, *wqh, *wql, *woh, *wol, *ah, *al;
    cudaGetSymbolAddress((void**)&xh, g_xh);   cudaGetSymbolAddress((void**)&xl, g_xl);
    cudaGetSymbolAddress((void**)&wqh, g_wqh); cudaGetSymbolAddress((void**)&wql, g_wql);
    cudaGetSymbolAddress((void**)&woh, g_woh); cudaGetSymbolAddress((void**)&wol, g_wol);
    cudaGetSymbolAddress((void**)&ah, g_ah);   cudaGetSymbolAddress((void**)&al, g_al);

    cudaFuncSetAttribute(swa_attn, cudaFuncAttributeMaxDynamicSharedMemorySize,
                         SM_FLOATS * (int)sizeof(float));
    cudaFuncSetAttribute(gemm_mma, cudaFuncAttributeMaxDynamicSharedMemorySize, GSMEM);

    const int M = NB * NT;

    // 0) hi/lo splits
    conv_split<<<M * NC / 1024, 256>>>(x, xh, xl, M * NC);
    conv_split<<<3 * NC * NC / 1024, 256>>>(w_qkv, wqh, wql, 3 * NC * NC);
    conv_split<<<NC * NC / 1024, 256>>>(w_o, woh, wol, NC * NC);

    // 1) QKV projection (tensor cores, mma.sync)
    gemm_mma<<<dim3(3 * NC / 128, M / 128), 256, GSMEM>>>(xh, xl, wqh, wql,
                                                          qkv_ptr, M, 3 * NC, NC);
    // 2) RoPE + head permute
    rope_split<<<M * NH, ND>>>();
    // 3) Sliding-window attention
    swa_attn<<<dim3(NT / BQ, NH, NB), 256, SM_FLOATS * sizeof(float)>>>();
    // 4) Output projection
    conv_split<<<M * NC / 1024, 256>>>(att_ptr, ah, al, M * NC);
    gemm_mma<<<dim3(NC / 128, M / 128), 256, GSMEM>>>(ah, al, woh, wol,
                                                      out, M, NC, NC);
}

// round 6
// speedup vs baseline: 7.8181x; 3.0834x over previous
#include <cuda_runtime.h>
#include <cuda_bf16.h>
#include <math.h>
#include <cstdint>

#define NB 2
#define NT 4096
#define NC 1024
#define NH 8
#define ND 128
#define NW 512

// ---------------- scratch (__device__ globals; no allocs allowed) ----------
__device__ float g_qkv[NB * NT * 3 * NC];   // [B*T, 3C]
__device__ float g_invf[64];

__device__ __align__(256) __nv_bfloat16 g_xh[NB * NT * NC], g_xl[NB * NT * NC];
__device__ __align__(256) __nv_bfloat16 g_wqh[3 * NC * NC], g_wql[3 * NC * NC];
__device__ __align__(256) __nv_bfloat16 g_woh[NC * NC],     g_wol[NC * NC];
__device__ __align__(256) __nv_bfloat16 g_ah[NB * NT * NC], g_al[NB * NT * NC];

__device__ __align__(256) __nv_bfloat16 g_qh[NB * NH * NT * ND], g_ql[NB * NH * NT * ND];
__device__ __align__(256) __nv_bfloat16 g_kh[NB * NH * NT * ND], g_kl[NB * NH * NT * ND];
__device__ __align__(256) __nv_bfloat16 g_vth[NB * NH * ND * NT], g_vtl[NB * NH * ND * NT]; // [bh][d][t]

// ---------------- helpers ---------------------------------------------------
__device__ __forceinline__ uint32_t smem_u32(const void* p) {
    uint32_t a;
    asm("{ .reg .u64 t; cvta.to.shared.u64 t, %1; cvt.u32.u64 %0, t; }" : "=r"(a) : "l"(p));
    return a;
}
__device__ __forceinline__ uint32_t toff(int r, int cu) {
    uint32_t o = ((uint32_t)(r >> 1) << 7) + ((uint32_t)(r & 1) << 6) + ((uint32_t)cu << 4);
    return o ^ ((o >> 3) & 0x70);
}
__device__ __forceinline__ uint32_t q_off(int r, int u)  { return (uint32_t)(r * 256 + ((u ^ (r & 7)) << 4)); }
__device__ __forceinline__ uint32_t vt_off(int r, int u) { return (uint32_t)(r * 128 + ((u ^ (r & 7)) << 4)); }

#define LDSM4(r0, r1, r2, r3, ad) \
    asm volatile("ldmatrix.sync.aligned.m8n8.x4.shared.b16 {%0,%1,%2,%3}, [%4];" \
                 : "=r"(r0), "=r"(r1), "=r"(r2), "=r"(r3) : "r"(ad))
#define LDSM4A(a, ad) LDSM4((a)[0], (a)[1], (a)[2], (a)[3], ad)

#define MMA16816(d, a0, a1, a2, a3, b0, b1) \
    asm volatile("mma.sync.aligned.m16n8k16.row.col.f32.bf16.bf16.f32 " \
                 "{%0,%1,%2,%3},{%4,%5,%6,%7},{%8,%9},{%0,%1,%2,%3};" \
                 : "+f"((d)[0]), "+f"((d)[1]), "+f"((d)[2]), "+f"((d)[3]) \
                 : "r"(a0), "r"(a1), "r"(a2), "r"(a3), "r"(b0), "r"(b1))

#define CP_ASYNC16(sa, ga) \
    asm volatile("cp.async.cg.shared.global [%0], [%1], 16;" :: "r"(sa), "l"(ga))
#define CP_COMMIT() asm volatile("cp.async.commit_group;" ::: "memory")
#define CP_WAIT1()  asm volatile("cp.async.wait_group 1;" ::: "memory")
#define CP_WAIT0()  asm volatile("cp.async.wait_group 0;" ::: "memory")

__device__ __forceinline__ void packsplit2(float a, float b, uint32_t& hi, uint32_t& lo) {
    __nv_bfloat16 ha = __float2bfloat16(a), hb = __float2bfloat16(b);
    __nv_bfloat162 hp; hp.x = ha; hp.y = hb;
    __nv_bfloat162 lp;
    lp.x = __float2bfloat16(a - __bfloat162float(ha));
    lp.y = __float2bfloat16(b - __bfloat162float(hb));
    hi = *reinterpret_cast<uint32_t*>(&hp);
    lo = *reinterpret_cast<uint32_t*>(&lp);
}
__device__ __forceinline__ void split_store2(__nv_bfloat16* H, __nv_bfloat16* L,
                                             size_t idx, float a, float b) {
    uint32_t hi, lo;
    packsplit2(a, b, hi, lo);
    *reinterpret_cast<uint32_t*>(&H[idx]) = hi;
    *reinterpret_cast<uint32_t*>(&L[idx]) = lo;
}

// ---------------------------------------------------------------------------
// fp32 -> (hi, lo) bf16 split
// ---------------------------------------------------------------------------
__global__ void conv_split(const float* __restrict__ s, __nv_bfloat16* __restrict__ h,
                           __nv_bfloat16* __restrict__ l, int n)
{
    int i = (blockIdx.x * 256 + threadIdx.x) * 4;
    if (i >= n) return;
    float4 v = *(const float4*)&s[i];
    float vv[4] = {v.x, v.y, v.z, v.w};
    __nv_bfloat16 hb[4], lb[4];
#pragma unroll
    for (int e = 0; e < 4; e++) {
        hb[e] = __float2bfloat16(vv[e]);
        lb[e] = __float2bfloat16(vv[e] - __bfloat162float(hb[e]));
    }
    *(uint2*)&h[i] = *(uint2*)hb;
    *(uint2*)&l[i] = *(uint2*)lb;
}

// ---------------------------------------------------------------------------
// GEMM: C[M,N] = A[M,K] . B[N,K]^T, bf16 hi/lo compensated (round-4 proven)
// ---------------------------------------------------------------------------
#define GSTAGE 32768
#define GSMEM  (2 * GSTAGE)

__global__ __launch_bounds__(256) void gemm_mma(
    const __nv_bfloat16* __restrict__ Ah, const __nv_bfloat16* __restrict__ Al,
    const __nv_bfloat16* __restrict__ Bh, const __nv_bfloat16* __restrict__ Bl,
    float* __restrict__ C, int M, int N, int K)
{
    extern __shared__ __align__(1024) char smem[];
    const uint32_t sb = smem_u32(smem);
    const int t = threadIdx.x;
    const int wid = t >> 5, lane = t & 31;
    const int m0 = blockIdx.y * 128, n0 = blockIdx.x * 128;
    const int wm = (wid & 3) * 32;
    const int wn = (wid >> 2) * 64;

    const size_t kb = (size_t)K * 2;
    const char* gA[4] = {
        (const char*)(Ah + (size_t)m0 * K), (const char*)(Al + (size_t)m0 * K),
        (const char*)(Bh + (size_t)n0 * K), (const char*)(Bl + (size_t)n0 * K)};

    const int r_ld = t >> 2, cu_ld = t & 3;
    const uint32_t so0 = toff(r_ld, cu_ld);
    const int r_ld2 = (t + 256) >> 2;
    const int cu_ld2 = (t + 256) & 3;
    const uint32_t so1 = toff(r_ld2 & 127, cu_ld2);

    const int nt = K / 32;

    auto issue = [&](int buf, int k0) {
        uint32_t stage = sb + buf * GSTAGE;
#pragma unroll
        for (int tile = 0; tile < 4; tile++) {
            const char* g = gA[tile] + (size_t)k0 * 2;
            uint32_t stb = stage + tile * 8192;
            CP_ASYNC16(stb + so0, g + (size_t)r_ld * kb + cu_ld * 16);
            CP_ASYNC16(stb + so1, g + (size_t)r_ld2 * kb + cu_ld2 * 16);
        }
        CP_COMMIT();
    };

    float acc[2][8][4];
#pragma unroll
    for (int i = 0; i < 2; i++)
#pragma unroll
        for (int j = 0; j < 8; j++)
#pragma unroll
            for (int e = 0; e < 4; e++) acc[i][j][e] = 0.f;

    issue(0, 0);

    const int a_row = (lane & 7) + ((lane >> 3) & 1) * 8;
    const int a_ku  = lane >> 4;
    const int b_row = (lane & 7) + ((lane >> 4) & 1) * 8;
    const int b_ku  = (lane >> 3) & 1;

    for (int tt = 0; tt < nt; tt++) {
        if (tt + 1 < nt) { issue((tt + 1) & 1, (tt + 1) * 32); CP_WAIT1(); }
        else             { CP_WAIT0(); }
        __syncthreads();

        const uint32_t stg = sb + (tt & 1) * GSTAGE;
#pragma unroll
        for (int ks = 0; ks < 2; ks++) {
            const int ku = ks * 2;
            uint32_t ah[2][4], al[2][4];
#pragma unroll
            for (int i = 0; i < 2; i++) {
                uint32_t ad = stg + toff(wm + i * 16 + a_row, ku + a_ku);
                LDSM4A(ah[i], ad);
                LDSM4A(al[i], ad + 8192);
            }
#pragma unroll
            for (int jj = 0; jj < 4; jj++) {
                uint32_t bd = stg + 16384 + toff(wn + jj * 16 + b_row, ku + b_ku);
                uint32_t bh[4], bl[4];
                LDSM4A(bh, bd);
                LDSM4A(bl, bd + 8192);
#pragma unroll
                for (int i = 0; i < 2; i++) {
                    MMA16816(acc[i][jj * 2],     ah[i][0], ah[i][1], ah[i][2], ah[i][3], bh[0], bh[1]);
                    MMA16816(acc[i][jj * 2],     ah[i][0], ah[i][1], ah[i][2], ah[i][3], bl[0], bl[1]);
                    MMA16816(acc[i][jj * 2],     al[i][0], al[i][1], al[i][2], al[i][3], bh[0], bh[1]);
                    MMA16816(acc[i][jj * 2 + 1], ah[i][0], ah[i][1], ah[i][2], ah[i][3], bh[2], bh[3]);
                    MMA16816(acc[i][jj * 2 + 1], ah[i][0], ah[i][1], ah[i][2], ah[i][3], bl[2], bl[3]);
                    MMA16816(acc[i][jj * 2 + 1], al[i][0], al[i][1], al[i][2], al[i][3], bh[2], bh[3]);
                }
            }
        }
        __syncthreads();
    }

#pragma unroll
    for (int i = 0; i < 2; i++) {
#pragma unroll
        for (int j = 0; j < 8; j++) {
            int row = m0 + wm + i * 16 + (lane >> 2);
            int col = n0 + wn + j * 8 + (lane & 3) * 2;
            *(float2*)&C[(size_t)row * N + col] = make_float2(acc[i][j][0], acc[i][j][1]);
            *(float2*)&C[(size_t)(row + 8) * N + col] = make_float2(acc[i][j][2], acc[i][j][3]);
        }
    }
}

// ---------------------------------------------------------------------------
// RoPE table + RoPE (q scale folded) -> bf16 hi/lo, and V transpose
// ---------------------------------------------------------------------------
__global__ void rope_tab()
{
    int j = threadIdx.x;
    if (j < 64) g_invf[j] = (float)pow(10000.0, -(double)j / 64.0);
}

__global__ void rope_qk()
{
    int bt   = blockIdx.x;
    int tpos = bt % NT;
    int b    = bt / NT;
    int d    = threadIdx.x;
    int j    = d & 63;

    float invf = g_invf[j];
    float ang = (float)tpos * invf;
    float cv = cosf(ang), sv = sinf(ang);
    float sgn = (d < 64) ? -1.f : 1.f;
    const float* base = g_qkv + (size_t)bt * (3 * NC);
    const float scale = 0.088388347648318447f;

#pragma unroll
    for (int h = 0; h < NH; h++) {
        float qv = base[h * ND + d];
        float qp = base[h * ND + (d ^ 64)];
        float kv = base[NC + h * ND + d];
        float kp = base[NC + h * ND + (d ^ 64)];
        float qo = (qv * cv + sgn * qp * sv) * scale;
        float ko = kv * cv + sgn * kp * sv;
        size_t oi = ((size_t)(b * NH + h) * NT + tpos) * ND + d;
        __nv_bfloat16 qh = __float2bfloat16(qo);
        __nv_bfloat16 kh = __float2bfloat16(ko);
        g_qh[oi] = qh; g_ql[oi] = __float2bfloat16(qo - __bfloat162float(qh));
        g_kh[oi] = kh; g_kl[oi] = __float2bfloat16(ko - __bfloat162float(kh));
    }
}

// V transpose: g_qkv v-part [bt][h*128+d] -> g_vth/g_vtl [bh][d][t]
__global__ void vt_split()
{
    __shared__ float tile[64][132];
    int t0 = blockIdx.x * 64;
    int h  = blockIdx.y;
    int b  = blockIdx.z;
    int t  = threadIdx.x;

#pragma unroll
    for (int i = 0; i < 8; i++) {
        int id = t + 256 * i;
        int r = id >> 5, c4 = (id & 31) * 4;
        float4 v = *(const float4*)&g_qkv[(size_t)(b * NT + t0 + r) * (3 * NC) + 2 * NC + h * ND + c4];
        *(float4*)&tile[r][c4] = v;
    }
    __syncthreads();

    int d = t >> 1, j0 = (t & 1) * 32;
    size_t out = ((size_t)(b * NH + h) * ND + d) * NT + t0 + j0;
#pragma unroll
    for (int jj = 0; jj < 32; jj += 2) {
        float v0 = tile[j0 + jj][d], v1 = tile[j0 + jj + 1][d];
        split_store2(g_vth, g_vtl, out + jj, v0, v1);
    }
}

// ---------------------------------------------------------------------------
// Sliding-window flash attention on mma.sync bf16, fully hi/lo compensated
// (Q, K, V, and now P). CTA: 128 queries; 8 warps = 16 rows x all keys.
// ---------------------------------------------------------------------------
#define AQ 128
#define AK 64
#define ASTG 65536
#define ATT_SMEM (65536 + 2 * ASTG)

__global__ __launch_bounds__(256, 1) void swa_mma()
{
    extern __shared__ __align__(1024) char smem[];
    const uint32_t sb = smem_u32(smem);
    const int t = threadIdx.x, wid = t >> 5, lane = t & 31;
    const int q0 = blockIdx.x * AQ;
    const int h = blockIdx.y, b = blockIdx.z;
    const int bh = b * NH + h;
    const size_t hoff = (size_t)bh * NT;

    const uint32_t QH = sb, QL = sb + 32768;

    {
        const char* gq_h = (const char*)(g_qh + (hoff + q0) * ND);
        const char* gq_l = (const char*)(g_ql + (hoff + q0) * ND);
#pragma unroll
        for (int i = 0; i < 8; i++) {
            int id = t + 256 * i;
            int r = id >> 4, u = id & 15;
            uint32_t off = q_off(r, u);
            CP_ASYNC16(QH + off, gq_h + (size_t)r * 256 + u * 16);
            CP_ASYNC16(QL + off, gq_l + (size_t)r * 256 + u * 16);
        }
        CP_COMMIT();
    }

    auto stage_load = [&](int buf, int kt) {
        uint32_t S = sb + 65536 + buf * ASTG;
        const char* gk_h = (const char*)(g_kh + (hoff + kt) * ND);
        const char* gk_l = (const char*)(g_kl + (hoff + kt) * ND);
#pragma unroll
        for (int i = 0; i < 4; i++) {
            int id = t + 256 * i;
            int r = id >> 4, u = id & 15;
            uint32_t off = q_off(r, u);
            CP_ASYNC16(S + off,         gk_h + (size_t)r * 256 + u * 16);
            CP_ASYNC16(S + 16384 + off, gk_l + (size_t)r * 256 + u * 16);
        }
#pragma unroll
        for (int i = 0; i < 4; i++) {
            int id = t + 256 * i;
            int r = id >> 3, u = id & 7;
            uint32_t off = vt_off(r, u);
            size_t gb = ((size_t)(bh * ND + r) * NT + kt + u * 8) * 2;
            CP_ASYNC16(S + 32768 + off, (const char*)g_vth + gb);
            CP_ASYNC16(S + 49152 + off, (const char*)g_vtl + gb);
        }
        CP_COMMIT();
    };

    int kt0 = q0 - NW; if (kt0 < 0) kt0 = 0;
    const int nt = (q0 + AQ - kt0) / AK;

    stage_load(0, kt0);

    float ov[16][4];
#pragma unroll
    for (int jj = 0; jj < 16; jj++)
#pragma unroll
        for (int e = 0; e < 4; e++) ov[jj][e] = 0.f;
    float mrow0 = -1e30f, mrow1 = -1e30f, lrow0 = 0.f, lrow1 = 0.f;

    const int wrow = wid * 16;
    const int a_row = (lane & 7) + ((lane >> 3) & 1) * 8;
    const int a_ku  = lane >> 4;
    const int b_row = (lane & 7) + ((lane >> 4) & 1) * 8;
    const int b_ku  = (lane >> 3) & 1;
    const int r0g = q0 + wrow + (lane >> 2);

    for (int tt = 0; tt < nt; tt++) {
        const int kt = kt0 + tt * AK;
        if (tt + 1 < nt) { stage_load((tt + 1) & 1, kt + AK); CP_WAIT1(); }
        else             { CP_WAIT0(); }
        __syncthreads();
        const uint32_t S = sb + 65536 + (tt & 1) * ASTG;

        // ---- S = Q.K^T (compensated) ----
        float sc[8][4];
#pragma unroll
        for (int f = 0; f < 8; f++)
#pragma unroll
            for (int e = 0; e < 4; e++) sc[f][e] = 0.f;

#pragma unroll
        for (int ku = 0; ku < 8; ku++) {
            uint32_t qh[4], ql[4];
            uint32_t qa = QH + q_off(wrow + a_row, 2 * ku + a_ku);
            LDSM4A(qh, qa);
            LDSM4A(ql, qa + 32768);
#pragma unroll
            for (int nj = 0; nj < 4; nj++) {
                uint32_t kh[4], kl[4];
                uint32_t ka = S + q_off(nj * 16 + b_row, 2 * ku + b_ku);
                LDSM4A(kh, ka);
                LDSM4A(kl, ka + 16384);
                MMA16816(sc[nj * 2],     qh[0], qh[1], qh[2], qh[3], kh[0], kh[1]);
                MMA16816(sc[nj * 2],     qh[0], qh[1], qh[2], qh[3], kl[0], kl[1]);
                MMA16816(sc[nj * 2],     ql[0], ql[1], ql[2], ql[3], kh[0], kh[1]);
                MMA16816(sc[nj * 2 + 1], qh[0], qh[1], qh[2], qh[3], kh[2], kh[3]);
                MMA16816(sc[nj * 2 + 1], qh[0], qh[1], qh[2], qh[3], kl[2], kl[3]);
                MMA16816(sc[nj * 2 + 1], ql[0], ql[1], ql[2], ql[3], kh[2], kh[3]);
            }
        }

        // ---- mask (only boundary tiles) ----
        const bool cmask = (kt + AK - 1 > q0 + wrow);
        const bool wmask = (kt < q0 + wrow + 15 - NW);
        if (cmask || wmask) {
#pragma unroll
            for (int f = 0; f < 8; f++) {
                int jb = kt + f * 8 + (lane & 3) * 2;
#pragma unroll
                for (int e = 0; e < 2; e++) {
                    int jg = jb + e;
                    if (jg > r0g || jg < r0g - NW)             sc[f][e]     = -1e30f;
                    if (jg > r0g + 8 || jg < r0g + 8 - NW)     sc[f][e + 2] = -1e30f;
                }
            }
        }

        // ---- online softmax (warp-local) ----
        float mt0 = -1e30f, mt1 = -1e30f;
#pragma unroll
        for (int f = 0; f < 8; f++) {
            mt0 = fmaxf(mt0, fmaxf(sc[f][0], sc[f][1]));
            mt1 = fmaxf(mt1, fmaxf(sc[f][2], sc[f][3]));
        }
        mt0 = fmaxf(mt0, __shfl_xor_sync(0xffffffffu, mt0, 1));
        mt0 = fmaxf(mt0, __shfl_xor_sync(0xffffffffu, mt0, 2));
        mt1 = fmaxf(mt1, __shfl_xor_sync(0xffffffffu, mt1, 1));
        mt1 = fmaxf(mt1, __shfl_xor_sync(0xffffffffu, mt1, 2));

        float mn0 = fmaxf(mrow0, mt0), mn1 = fmaxf(mrow1, mt1);
        float al0 = __expf(mrow0 - mn0), al1 = __expf(mrow1 - mn1);
        mrow0 = mn0; mrow1 = mn1;

        float rs0 = 0.f, rs1 = 0.f;
#pragma unroll
        for (int f = 0; f < 8; f++) {
            sc[f][0] = __expf(sc[f][0] - mn0);
            sc[f][1] = __expf(sc[f][1] - mn0);
            sc[f][2] = __expf(sc[f][2] - mn1);
            sc[f][3] = __expf(sc[f][3] - mn1);
            rs0 += sc[f][0] + sc[f][1];
            rs1 += sc[f][2] + sc[f][3];
        }
        rs0 += __shfl_xor_sync(0xffffffffu, rs0, 1);
        rs0 += __shfl_xor_sync(0xffffffffu, rs0, 2);
        rs1 += __shfl_xor_sync(0xffffffffu, rs1, 1);
        rs1 += __shfl_xor_sync(0xffffffffu, rs1, 2);
        lrow0 = lrow0 * al0 + rs0;
        lrow1 = lrow1 * al1 + rs1;

#pragma unroll
        for (int jj = 0; jj < 16; jj++) {
            ov[jj][0] *= al0; ov[jj][1] *= al0;
            ov[jj][2] *= al1; ov[jj][3] *= al1;
        }

        // ---- O += P.V with P hi/lo compensation (ph.Vh + ph.Vl + pl.Vh) ----
#pragma unroll
        for (int ks = 0; ks < 4; ks++) {
            uint32_t ph0, pl0, ph1, pl1, ph2, pl2, ph3, pl3;
            packsplit2(sc[2 * ks][0],     sc[2 * ks][1],     ph0, pl0);
            packsplit2(sc[2 * ks][2],     sc[2 * ks][3],     ph1, pl1);
            packsplit2(sc[2 * ks + 1][0], sc[2 * ks + 1][1], ph2, pl2);
            packsplit2(sc[2 * ks + 1][2], sc[2 * ks + 1][3], ph3, pl3);
#pragma unroll
            for (int nj = 0; nj < 8; nj++) {
                uint32_t vh[4], vl[4];
                uint32_t va = S + 32768 + vt_off(nj * 16 + b_row, ks * 2 + b_ku);
                LDSM4A(vh, va);
                LDSM4A(vl, va + 16384);
                MMA16816(ov[nj * 2],     ph0, ph1, ph2, ph3, vh[0], vh[1]);
                MMA16816(ov[nj * 2],     ph0, ph1, ph2, ph3, vl[0], vl[1]);
                MMA16816(ov[nj * 2],     pl0, pl1, pl2, pl3, vh[0], vh[1]);
                MMA16816(ov[nj * 2 + 1], ph0, ph1, ph2, ph3, vh[2], vh[3]);
                MMA16816(ov[nj * 2 + 1], ph0, ph1, ph2, ph3, vl[2], vl[3]);
                MMA16816(ov[nj * 2 + 1], pl0, pl1, pl2, pl3, vh[2], vh[3]);
            }
        }
        __syncthreads();
    }

    // ---- finalize: write hi/lo bf16 directly for the out-projection ----
    float i0 = 1.f / lrow0, i1 = 1.f / lrow1;
    size_t row0 = (size_t)(b * NT + r0g) * NC;
    size_t row1 = row0 + 8 * NC;
#pragma unroll
    for (int jj = 0; jj < 16; jj++) {
        int c = h * ND + jj * 8 + (lane & 3) * 2;
        split_store2(g_ah, g_al, row0 + c, ov[jj][0] * i0, ov[jj][1] * i0);
        split_store2(g_ah, g_al, row1 + c, ov[jj][2] * i1, ov[jj][3] * i1);
    }
}

// ---------------------------------------------------------------------------
extern "C" void kernel_launch(void* const* d_in, const int* in_sizes, int n_in,
                              void* d_out, int out_size)
{
    const float* x     = (const float*)d_in[0];
    const float* w_qkv = (const float*)d_in[1];
    const float* w_o   = (const float*)d_in[2];
    float* out = (float*)d_out;

    float* qkv_ptr;
    cudaGetSymbolAddress((void**)&qkv_ptr, g_qkv);
    __nv_bfloat16 *xh, *xl, *wqh, *wql, *woh, *wol, *ah, *al;
    cudaGetSymbolAddress((void**)&xh, g_xh);   cudaGetSymbolAddress((void**)&xl, g_xl);
    cudaGetSymbolAddress((void**)&wqh, g_wqh); cudaGetSymbolAddress((void**)&wql, g_wql);
    cudaGetSymbolAddress((void**)&woh, g_woh); cudaGetSymbolAddress((void**)&wol, g_wol);
    cudaGetSymbolAddress((void**)&ah, g_ah);   cudaGetSymbolAddress((void**)&al, g_al);

    cudaFuncSetAttribute(gemm_mma, cudaFuncAttributeMaxDynamicSharedMemorySize, GSMEM);
    cudaFuncSetAttribute(swa_mma, cudaFuncAttributeMaxDynamicSharedMemorySize, ATT_SMEM);

    const int M = NB * NT;

    rope_tab<<<1, 64>>>();
    conv_split<<<M * NC / 1024, 256>>>(x, xh, xl, M * NC);
    conv_split<<<3 * NC * NC / 1024, 256>>>(w_qkv, wqh, wql, 3 * NC * NC);
    conv_split<<<NC * NC / 1024, 256>>>(w_o, woh, wol, NC * NC);

    gemm_mma<<<dim3(3 * NC / 128, M / 128), 256, GSMEM>>>(xh, xl, wqh, wql,
                                                          qkv_ptr, M, 3 * NC, NC);
    rope_qk<<<M, ND>>>();
    vt_split<<<dim3(NT / 64, NH, NB), 256>>>();

    swa_mma<<<dim3(NT / AQ, NH, NB), 256, ATT_SMEM>>>();

    gemm_mma<<<dim3(NC / 128, M / 128), 256, GSMEM>>>(ah, al, woh, wol,
                                                      out, M, NC, NC);
}

// round 7
// speedup vs baseline: 8.7871x; 1.1240x over previous
#include <cuda_runtime.h>
#include <cuda_bf16.h>
#include <math.h>
#include <cstdint>

#define NB 2
#define NT 4096
#define NC 1024
#define NH 8
#define ND 128
#define NW 512

// ---------------- scratch (__device__ globals; no allocs allowed) ----------
__device__ float g_qkv[NB * NT * 3 * NC];   // [B*T, 3C]
__device__ float g_invf[64];

__device__ __align__(256) __nv_bfloat16 g_xh[NB * NT * NC], g_xl[NB * NT * NC];
__device__ __align__(256) __nv_bfloat16 g_wqh[3 * NC * NC], g_wql[3 * NC * NC];
__device__ __align__(256) __nv_bfloat16 g_woh[NC * NC],     g_wol[NC * NC];
__device__ __align__(256) __nv_bfloat16 g_ah[NB * NT * NC], g_al[NB * NT * NC];

__device__ __align__(256) __nv_bfloat16 g_qh[NB * NH * NT * ND], g_ql[NB * NH * NT * ND];
__device__ __align__(256) __nv_bfloat16 g_kh[NB * NH * NT * ND], g_kl[NB * NH * NT * ND];
__device__ __align__(256) __nv_bfloat16 g_vth[NB * NH * ND * NT], g_vtl[NB * NH * ND * NT]; // [bh][d][t]

// ---------------- helpers ---------------------------------------------------
__device__ __forceinline__ uint32_t smem_u32(const void* p) {
    uint32_t a;
    asm("{ .reg .u64 t; cvta.to.shared.u64 t, %1; cvt.u32.u64 %0, t; }" : "=r"(a) : "l"(p));
    return a;
}
__device__ __forceinline__ uint32_t toff(int r, int cu) {
    uint32_t o = ((uint32_t)(r >> 1) << 7) + ((uint32_t)(r & 1) << 6) + ((uint32_t)cu << 4);
    return o ^ ((o >> 3) & 0x70);
}
__device__ __forceinline__ uint32_t q_off(int r, int u)  { return (uint32_t)(r * 256 + ((u ^ (r & 7)) << 4)); }
__device__ __forceinline__ uint32_t vt_off(int r, int u) { return (uint32_t)(r * 128 + ((u ^ (r & 7)) << 4)); }

#define LDSM4(r0, r1, r2, r3, ad) \
    asm volatile("ldmatrix.sync.aligned.m8n8.x4.shared.b16 {%0,%1,%2,%3}, [%4];" \
                 : "=r"(r0), "=r"(r1), "=r"(r2), "=r"(r3) : "r"(ad))
#define LDSM4A(a, ad) LDSM4((a)[0], (a)[1], (a)[2], (a)[3], ad)

#define MMA16816(d, a0, a1, a2, a3, b0, b1) \
    asm volatile("mma.sync.aligned.m16n8k16.row.col.f32.bf16.bf16.f32 " \
                 "{%0,%1,%2,%3},{%4,%5,%6,%7},{%8,%9},{%0,%1,%2,%3};" \
                 : "+f"((d)[0]), "+f"((d)[1]), "+f"((d)[2]), "+f"((d)[3]) \
                 : "r"(a0), "r"(a1), "r"(a2), "r"(a3), "r"(b0), "r"(b1))

#define CP_ASYNC16(sa, ga) \
    asm volatile("cp.async.cg.shared.global [%0], [%1], 16;" :: "r"(sa), "l"(ga))
#define CP_COMMIT() asm volatile("cp.async.commit_group;" ::: "memory")
#define CP_WAIT1()  asm volatile("cp.async.wait_group 1;" ::: "memory")
#define CP_WAIT0()  asm volatile("cp.async.wait_group 0;" ::: "memory")

__device__ __forceinline__ void packsplit2(float a, float b, uint32_t& hi, uint32_t& lo) {
    __nv_bfloat16 ha = __float2bfloat16(a), hb = __float2bfloat16(b);
    __nv_bfloat162 hp; hp.x = ha; hp.y = hb;
    __nv_bfloat162 lp;
    lp.x = __float2bfloat16(a - __bfloat162float(ha));
    lp.y = __float2bfloat16(b - __bfloat162float(hb));
    hi = *reinterpret_cast<uint32_t*>(&hp);
    lo = *reinterpret_cast<uint32_t*>(&lp);
}
__device__ __forceinline__ void split_store2(__nv_bfloat16* H, __nv_bfloat16* L,
                                             size_t idx, float a, float b) {
    uint32_t hi, lo;
    packsplit2(a, b, hi, lo);
    *reinterpret_cast<uint32_t*>(&H[idx]) = hi;
    *reinterpret_cast<uint32_t*>(&L[idx]) = lo;
}

// ---------------------------------------------------------------------------
// fp32 -> (hi, lo) bf16 split
// ---------------------------------------------------------------------------
__global__ void conv_split(const float* __restrict__ s, __nv_bfloat16* __restrict__ h,
                           __nv_bfloat16* __restrict__ l, int n)
{
    int i = (blockIdx.x * 256 + threadIdx.x) * 4;
    if (i >= n) return;
    float4 v = *(const float4*)&s[i];
    float vv[4] = {v.x, v.y, v.z, v.w};
    __nv_bfloat16 hb[4], lb[4];
#pragma unroll
    for (int e = 0; e < 4; e++) {
        hb[e] = __float2bfloat16(vv[e]);
        lb[e] = __float2bfloat16(vv[e] - __bfloat162float(hb[e]));
    }
    *(uint2*)&h[i] = *(uint2*)hb;
    *(uint2*)&l[i] = *(uint2*)lb;
}

// ---------------------------------------------------------------------------
// GEMM: C[M,N] = A[M,K] . B[N,K]^T, bf16 hi/lo compensated.
// 3-stage cp.async pipeline, ONE __syncthreads per K-tile.
// ---------------------------------------------------------------------------
#define GSTAGE 32768
#define GSMEM  (3 * GSTAGE)

__global__ __launch_bounds__(256) void gemm_mma(
    const __nv_bfloat16* __restrict__ Ah, const __nv_bfloat16* __restrict__ Al,
    const __nv_bfloat16* __restrict__ Bh, const __nv_bfloat16* __restrict__ Bl,
    float* __restrict__ C, int M, int N, int K)
{
    extern __shared__ __align__(1024) char smem[];
    const uint32_t sb = smem_u32(smem);
    const int t = threadIdx.x;
    const int wid = t >> 5, lane = t & 31;
    const int m0 = blockIdx.y * 128, n0 = blockIdx.x * 128;
    const int wm = (wid & 3) * 32;
    const int wn = (wid >> 2) * 64;

    const size_t kb = (size_t)K * 2;
    const char* gA[4] = {
        (const char*)(Ah + (size_t)m0 * K), (const char*)(Al + (size_t)m0 * K),
        (const char*)(Bh + (size_t)n0 * K), (const char*)(Bl + (size_t)n0 * K)};

    const int r_ld = t >> 2, cu_ld = t & 3;
    const uint32_t so0 = toff(r_ld, cu_ld);
    const int r_ld2 = (t + 256) >> 2;
    const int cu_ld2 = (t + 256) & 3;
    const uint32_t so1 = toff(r_ld2 & 127, cu_ld2);

    const int nt = K / 32;

    auto issue = [&](int stage, int k0) {
        uint32_t sg = sb + stage * GSTAGE;
#pragma unroll
        for (int tile = 0; tile < 4; tile++) {
            const char* g = gA[tile] + (size_t)k0 * 2;
            uint32_t stb = sg + tile * 8192;
            CP_ASYNC16(stb + so0, g + (size_t)r_ld * kb + cu_ld * 16);
            CP_ASYNC16(stb + so1, g + (size_t)r_ld2 * kb + cu_ld2 * 16);
        }
        CP_COMMIT();
    };

    float acc[2][8][4];
#pragma unroll
    for (int i = 0; i < 2; i++)
#pragma unroll
        for (int j = 0; j < 8; j++)
#pragma unroll
            for (int e = 0; e < 4; e++) acc[i][j][e] = 0.f;

    // prologue: stages 0,1 in flight
    issue(0, 0);
    issue(1, 32);

    const int a_row = (lane & 7) + ((lane >> 3) & 1) * 8;
    const int a_ku  = lane >> 4;
    const int b_row = (lane & 7) + ((lane >> 4) & 1) * 8;
    const int b_ku  = (lane >> 3) & 1;

    int stage = 0, nstage = 2;   // nstage = next stage index to fill
    for (int tt = 0; tt < nt; tt++) {
        CP_WAIT1();              // group tt complete (≤1 pending)
        __syncthreads();         // all warps done with stage being overwritten

        if (tt + 2 < nt) { issue(nstage, (tt + 2) * 32); }
        else             { CP_COMMIT(); }   // empty group keeps accounting uniform
        nstage = (nstage == 2) ? 0 : nstage + 1;

        const uint32_t stg = sb + stage * GSTAGE;
        stage = (stage == 2) ? 0 : stage + 1;

#pragma unroll
        for (int ks = 0; ks < 2; ks++) {
            const int ku = ks * 2;
            uint32_t ah[2][4], al[2][4];
#pragma unroll
            for (int i = 0; i < 2; i++) {
                uint32_t ad = stg + toff(wm + i * 16 + a_row, ku + a_ku);
                LDSM4A(ah[i], ad);
                LDSM4A(al[i], ad + 8192);
            }
#pragma unroll
            for (int jj = 0; jj < 4; jj++) {
                uint32_t bd = stg + 16384 + toff(wn + jj * 16 + b_row, ku + b_ku);
                uint32_t bh[4], bl[4];
                LDSM4A(bh, bd);
                LDSM4A(bl, bd + 8192);
#pragma unroll
                for (int i = 0; i < 2; i++) {
                    MMA16816(acc[i][jj * 2],     ah[i][0], ah[i][1], ah[i][2], ah[i][3], bh[0], bh[1]);
                    MMA16816(acc[i][jj * 2],     ah[i][0], ah[i][1], ah[i][2], ah[i][3], bl[0], bl[1]);
                    MMA16816(acc[i][jj * 2],     al[i][0], al[i][1], al[i][2], al[i][3], bh[0], bh[1]);
                    MMA16816(acc[i][jj * 2 + 1], ah[i][0], ah[i][1], ah[i][2], ah[i][3], bh[2], bh[3]);
                    MMA16816(acc[i][jj * 2 + 1], ah[i][0], ah[i][1], ah[i][2], ah[i][3], bl[2], bl[3]);
                    MMA16816(acc[i][jj * 2 + 1], al[i][0], al[i][1], al[i][2], al[i][3], bh[2], bh[3]);
                }
            }
        }
    }

#pragma unroll
    for (int i = 0; i < 2; i++) {
#pragma unroll
        for (int j = 0; j < 8; j++) {
            int row = m0 + wm + i * 16 + (lane >> 2);
            int col = n0 + wn + j * 8 + (lane & 3) * 2;
            *(float2*)&C[(size_t)row * N + col] = make_float2(acc[i][j][0], acc[i][j][1]);
            *(float2*)&C[(size_t)(row + 8) * N + col] = make_float2(acc[i][j][2], acc[i][j][3]);
        }
    }
}

// ---------------------------------------------------------------------------
// RoPE table + RoPE (q scale folded) -> bf16 hi/lo, and V transpose
// ---------------------------------------------------------------------------
__global__ void rope_tab()
{
    int j = threadIdx.x;
    if (j < 64) g_invf[j] = (float)pow(10000.0, -(double)j / 64.0);
}

__global__ void rope_qk()
{
    int bt   = blockIdx.x;
    int tpos = bt % NT;
    int b    = bt / NT;
    int d    = threadIdx.x;
    int j    = d & 63;

    float invf = g_invf[j];
    float ang = (float)tpos * invf;
    float cv = cosf(ang), sv = sinf(ang);
    float sgn = (d < 64) ? -1.f : 1.f;
    const float* base = g_qkv + (size_t)bt * (3 * NC);
    const float scale = 0.088388347648318447f;

#pragma unroll
    for (int h = 0; h < NH; h++) {
        float qv = base[h * ND + d];
        float qp = base[h * ND + (d ^ 64)];
        float kv = base[NC + h * ND + d];
        float kp = base[NC + h * ND + (d ^ 64)];
        float qo = (qv * cv + sgn * qp * sv) * scale;
        float ko = kv * cv + sgn * kp * sv;
        size_t oi = ((size_t)(b * NH + h) * NT + tpos) * ND + d;
        __nv_bfloat16 qh = __float2bfloat16(qo);
        __nv_bfloat16 kh = __float2bfloat16(ko);
        g_qh[oi] = qh; g_ql[oi] = __float2bfloat16(qo - __bfloat162float(qh));
        g_kh[oi] = kh; g_kl[oi] = __float2bfloat16(ko - __bfloat162float(kh));
    }
}

// V transpose: g_qkv v-part [bt][h*128+d] -> g_vth/g_vtl [bh][d][t]
__global__ void vt_split()
{
    __shared__ float tile[64][132];
    int t0 = blockIdx.x * 64;
    int h  = blockIdx.y;
    int b  = blockIdx.z;
    int t  = threadIdx.x;

#pragma unroll
    for (int i = 0; i < 8; i++) {
        int id = t + 256 * i;
        int r = id >> 5, c4 = (id & 31) * 4;
        float4 v = *(const float4*)&g_qkv[(size_t)(b * NT + t0 + r) * (3 * NC) + 2 * NC + h * ND + c4];
        *(float4*)&tile[r][c4] = v;
    }
    __syncthreads();

    int d = t >> 1, j0 = (t & 1) * 32;
    size_t out = ((size_t)(b * NH + h) * ND + d) * NT + t0 + j0;
#pragma unroll
    for (int jj = 0; jj < 32; jj += 2) {
        float v0 = tile[j0 + jj][d], v1 = tile[j0 + jj + 1][d];
        split_store2(g_vth, g_vtl, out + jj, v0, v1);
    }
}

// ---------------------------------------------------------------------------
// Sliding-window flash attention on mma.sync bf16, fully hi/lo compensated.
// CTA: 128 queries; 8 warps = 16 rows x all keys. Warp-level tile skipping
// for tiles fully outside the warp's causal/window range.
// ---------------------------------------------------------------------------
#define AQ 128
#define AK 64
#define ASTG 65536
#define ATT_SMEM (65536 + 2 * ASTG)

__global__ __launch_bounds__(256, 1) void swa_mma()
{
    extern __shared__ __align__(1024) char smem[];
    const uint32_t sb = smem_u32(smem);
    const int t = threadIdx.x, wid = t >> 5, lane = t & 31;
    const int q0 = blockIdx.x * AQ;
    const int h = blockIdx.y, b = blockIdx.z;
    const int bh = b * NH + h;
    const size_t hoff = (size_t)bh * NT;

    const uint32_t QH = sb, QL = sb + 32768;

    {
        const char* gq_h = (const char*)(g_qh + (hoff + q0) * ND);
        const char* gq_l = (const char*)(g_ql + (hoff + q0) * ND);
#pragma unroll
        for (int i = 0; i < 8; i++) {
            int id = t + 256 * i;
            int r = id >> 4, u = id & 15;
            uint32_t off = q_off(r, u);
            CP_ASYNC16(QH + off, gq_h + (size_t)r * 256 + u * 16);
            CP_ASYNC16(QL + off, gq_l + (size_t)r * 256 + u * 16);
        }
        CP_COMMIT();
    }

    auto stage_load = [&](int buf, int kt) {
        uint32_t S = sb + 65536 + buf * ASTG;
        const char* gk_h = (const char*)(g_kh + (hoff + kt) * ND);
        const char* gk_l = (const char*)(g_kl + (hoff + kt) * ND);
#pragma unroll
        for (int i = 0; i < 4; i++) {
            int id = t + 256 * i;
            int r = id >> 4, u = id & 15;
            uint32_t off = q_off(r, u);
            CP_ASYNC16(S + off,         gk_h + (size_t)r * 256 + u * 16);
            CP_ASYNC16(S + 16384 + off, gk_l + (size_t)r * 256 + u * 16);
        }
#pragma unroll
        for (int i = 0; i < 4; i++) {
            int id = t + 256 * i;
            int r = id >> 3, u = id & 7;
            uint32_t off = vt_off(r, u);
            size_t gb = ((size_t)(bh * ND + r) * NT + kt + u * 8) * 2;
            CP_ASYNC16(S + 32768 + off, (const char*)g_vth + gb);
            CP_ASYNC16(S + 49152 + off, (const char*)g_vtl + gb);
        }
        CP_COMMIT();
    };

    int kt0 = q0 - NW; if (kt0 < 0) kt0 = 0;
    const int nt = (q0 + AQ - kt0) / AK;

    stage_load(0, kt0);

    float ov[16][4];
#pragma unroll
    for (int jj = 0; jj < 16; jj++)
#pragma unroll
        for (int e = 0; e < 4; e++) ov[jj][e] = 0.f;
    float mrow0 = -1e30f, mrow1 = -1e30f, lrow0 = 0.f, lrow1 = 0.f;

    const int wrow = wid * 16;
    const int a_row = (lane & 7) + ((lane >> 3) & 1) * 8;
    const int a_ku  = lane >> 4;
    const int b_row = (lane & 7) + ((lane >> 4) & 1) * 8;
    const int b_ku  = (lane >> 3) & 1;
    const int r0g = q0 + wrow + (lane >> 2);

    for (int tt = 0; tt < nt; tt++) {
        const int kt = kt0 + tt * AK;
        if (tt + 1 < nt) { stage_load((tt + 1) & 1, kt + AK); CP_WAIT1(); }
        else             { CP_WAIT0(); }
        __syncthreads();
        const uint32_t S = sb + 65536 + (tt & 1) * ASTG;

        // warp-level skip: tile fully outside this warp's causal/window range
        const bool active = (kt <= q0 + wrow + 15) && (kt + AK - 1 >= q0 + wrow - NW);
        if (active) {

        // ---- S = Q.K^T (compensated) ----
        float sc[8][4];
#pragma unroll
        for (int f = 0; f < 8; f++)
#pragma unroll
            for (int e = 0; e < 4; e++) sc[f][e] = 0.f;

#pragma unroll
        for (int ku = 0; ku < 8; ku++) {
            uint32_t qh[4], ql[4];
            uint32_t qa = QH + q_off(wrow + a_row, 2 * ku + a_ku);
            LDSM4A(qh, qa);
            LDSM4A(ql, qa + 32768);
#pragma unroll
            for (int nj = 0; nj < 4; nj++) {
                uint32_t kh[4], kl[4];
                uint32_t ka = S + q_off(nj * 16 + b_row, 2 * ku + b_ku);
                LDSM4A(kh, ka);
                LDSM4A(kl, ka + 16384);
                MMA16816(sc[nj * 2],     qh[0], qh[1], qh[2], qh[3], kh[0], kh[1]);
                MMA16816(sc[nj * 2],     qh[0], qh[1], qh[2], qh[3], kl[0], kl[1]);
                MMA16816(sc[nj * 2],     ql[0], ql[1], ql[2], ql[3], kh[0], kh[1]);
                MMA16816(sc[nj * 2 + 1], qh[0], qh[1], qh[2], qh[3], kh[2], kh[3]);
                MMA16816(sc[nj * 2 + 1], qh[0], qh[1], qh[2], qh[3], kl[2], kl[3]);
                MMA16816(sc[nj * 2 + 1], ql[0], ql[1], ql[2], ql[3], kh[2], kh[3]);
            }
        }

        // ---- mask (only boundary tiles) ----
        const bool cmask = (kt + AK - 1 > q0 + wrow);
        const bool wmask = (kt < q0 + wrow + 15 - NW);
        if (cmask || wmask) {
#pragma unroll
            for (int f = 0; f < 8; f++) {
                int jb = kt + f * 8 + (lane & 3) * 2;
#pragma unroll
                for (int e = 0; e < 2; e++) {
                    int jg = jb + e;
                    if (jg > r0g || jg < r0g - NW)             sc[f][e]     = -1e30f;
                    if (jg > r0g + 8 || jg < r0g + 8 - NW)     sc[f][e + 2] = -1e30f;
                }
            }
        }

        // ---- online softmax (warp-local) ----
        float mt0 = -1e30f, mt1 = -1e30f;
#pragma unroll
        for (int f = 0; f < 8; f++) {
            mt0 = fmaxf(mt0, fmaxf(sc[f][0], sc[f][1]));
            mt1 = fmaxf(mt1, fmaxf(sc[f][2], sc[f][3]));
        }
        mt0 = fmaxf(mt0, __shfl_xor_sync(0xffffffffu, mt0, 1));
        mt0 = fmaxf(mt0, __shfl_xor_sync(0xffffffffu, mt0, 2));
        mt1 = fmaxf(mt1, __shfl_xor_sync(0xffffffffu, mt1, 1));
        mt1 = fmaxf(mt1, __shfl_xor_sync(0xffffffffu, mt1, 2));

        float mn0 = fmaxf(mrow0, mt0), mn1 = fmaxf(mrow1, mt1);
        float al0 = __expf(mrow0 - mn0), al1 = __expf(mrow1 - mn1);
        mrow0 = mn0; mrow1 = mn1;

        float rs0 = 0.f, rs1 = 0.f;
#pragma unroll
        for (int f = 0; f < 8; f++) {
            sc[f][0] = __expf(sc[f][0] - mn0);
            sc[f][1] = __expf(sc[f][1] - mn0);
            sc[f][2] = __expf(sc[f][2] - mn1);
            sc[f][3] = __expf(sc[f][3] - mn1);
            rs0 += sc[f][0] + sc[f][1];
            rs1 += sc[f][2] + sc[f][3];
        }
        rs0 += __shfl_xor_sync(0xffffffffu, rs0, 1);
        rs0 += __shfl_xor_sync(0xffffffffu, rs0, 2);
        rs1 += __shfl_xor_sync(0xffffffffu, rs1, 1);
        rs1 += __shfl_xor_sync(0xffffffffu, rs1, 2);
        lrow0 = lrow0 * al0 + rs0;
        lrow1 = lrow1 * al1 + rs1;

#pragma unroll
        for (int jj = 0; jj < 16; jj++) {
            ov[jj][0] *= al0; ov[jj][1] *= al0;
            ov[jj][2] *= al1; ov[jj][3] *= al1;
        }

        // ---- O += P.V with P hi/lo compensation ----
#pragma unroll
        for (int ks = 0; ks < 4; ks++) {
            uint32_t ph0, pl0, ph1, pl1, ph2, pl2, ph3, pl3;
            packsplit2(sc[2 * ks][0],     sc[2 * ks][1],     ph0, pl0);
            packsplit2(sc[2 * ks][2],     sc[2 * ks][3],     ph1, pl1);
            packsplit2(sc[2 * ks + 1][0], sc[2 * ks + 1][1], ph2, pl2);
            packsplit2(sc[2 * ks + 1][2], sc[2 * ks + 1][3], ph3, pl3);
#pragma unroll
            for (int nj = 0; nj < 8; nj++) {
                uint32_t vh[4], vl[4];
                uint32_t va = S + 32768 + vt_off(nj * 16 + b_row, ks * 2 + b_ku);
                LDSM4A(vh, va);
                LDSM4A(vl, va + 16384);
                MMA16816(ov[nj * 2],     ph0, ph1, ph2, ph3, vh[0], vh[1]);
                MMA16816(ov[nj * 2],     ph0, ph1, ph2, ph3, vl[0], vl[1]);
                MMA16816(ov[nj * 2],     pl0, pl1, pl2, pl3, vh[0], vh[1]);
                MMA16816(ov[nj * 2 + 1], ph0, ph1, ph2, ph3, vh[2], vh[3]);
                MMA16816(ov[nj * 2 + 1], ph0, ph1, ph2, ph3, vl[2], vl[3]);
                MMA16816(ov[nj * 2 + 1], pl0, pl1, pl2, pl3, vh[2], vh[3]);
            }
        }

        }   // active
        __syncthreads();
    }

    // ---- finalize: write hi/lo bf16 directly for the out-projection ----
    float i0 = 1.f / lrow0, i1 = 1.f / lrow1;
    size_t row0 = (size_t)(b * NT + r0g) * NC;
    size_t row1 = row0 + 8 * NC;
#pragma unroll
    for (int jj = 0; jj < 16; jj++) {
        int c = h * ND + jj * 8 + (lane & 3) * 2;
        split_store2(g_ah, g_al, row0 + c, ov[jj][0] * i0, ov[jj][1] * i0);
        split_store2(g_ah, g_al, row1 + c, ov[jj][2] * i1, ov[jj][3] * i1);
    }
}

// ---------------------------------------------------------------------------
extern "C" void kernel_launch(void* const* d_in, const int* in_sizes, int n_in,
                              void* d_out, int out_size)
{
    const float* x     = (const float*)d_in[0];
    const float* w_qkv = (const float*)d_in[1];
    const float* w_o   = (const float*)d_in[2];
    float* out = (float*)d_out;

    float* qkv_ptr;
    cudaGetSymbolAddress((void**)&qkv_ptr, g_qkv);
    __nv_bfloat16 *xh, *xl, *wqh, *wql, *woh, *wol, *ah, *al;
    cudaGetSymbolAddress((void**)&xh, g_xh);   cudaGetSymbolAddress((void**)&xl, g_xl);
    cudaGetSymbolAddress((void**)&wqh, g_wqh); cudaGetSymbolAddress((void**)&wql, g_wql);
    cudaGetSymbolAddress((void**)&woh, g_woh); cudaGetSymbolAddress((void**)&wol, g_wol);
    cudaGetSymbolAddress((void**)&ah, g_ah);   cudaGetSymbolAddress((void**)&al, g_al);

    cudaFuncSetAttribute(gemm_mma, cudaFuncAttributeMaxDynamicSharedMemorySize, GSMEM);
    cudaFuncSetAttribute(swa_mma, cudaFuncAttributeMaxDynamicSharedMemorySize, ATT_SMEM);

    const int M = NB * NT;

    rope_tab<<<1, 64>>>();
    conv_split<<<M * NC / 1024, 256>>>(x, xh, xl, M * NC);
    conv_split<<<3 * NC * NC / 1024, 256>>>(w_qkv, wqh, wql, 3 * NC * NC);
    conv_split<<<NC * NC / 1024, 256>>>(w_o, woh, wol, NC * NC);

    gemm_mma<<<dim3(3 * NC / 128, M / 128), 256, GSMEM>>>(xh, xl, wqh, wql,
                                                          qkv_ptr, M, 3 * NC, NC);
    rope_qk<<<M, ND>>>();
    vt_split<<<dim3(NT / 64, NH, NB), 256>>>();

    swa_mma<<<dim3(NT / AQ, NH, NB), 256, ATT_SMEM>>>();

    gemm_mma<<<dim3(NC / 128, M / 128), 256, GSMEM>>>(ah, al, woh, wol,
                                                      out, M, NC, NC);
}